// round 2
// baseline (speedup 1.0000x reference)
#include <cuda_runtime.h>

#define NN 100000
#define EE 600000
#define HH 128
#define LL 3
#define BB 16
#define CATW 512   // (LL+1)*HH

// ---- scratch (device globals: no allocation allowed) ----
__device__ float g_cat[(size_t)NN * CATW];   // all_h concatenated [N, 4*128]
__device__ float g_agg[(size_t)NN * HH];     // per-layer aggregation
__device__ float g_pool[BB * HH];            // graph sum pool
__device__ int   g_cnt[BB];                  // nodes per graph

// ---------------------------------------------------------------- zero kernels
__global__ __launch_bounds__(256) void zero_agg_k() {
    int i = blockIdx.x * 256 + threadIdx.x;       // grid covers NN*HH/4 float4
    float4 z = make_float4(0.f, 0.f, 0.f, 0.f);
    ((float4*)g_agg)[i] = z;
}

__global__ __launch_bounds__(256) void zero_pool_k() {
    int i = blockIdx.x * 256 + threadIdx.x;
    if (i < BB * HH) g_pool[i] = 0.f;
    if (i < BB) g_cnt[i] = 0;
}

// ---------------------------------------------------------------- input proj
// h0 = x @ in_W + in_b   (K=12), writes layer-0 slice of g_cat
__global__ __launch_bounds__(256) void in_proj_k(const float* __restrict__ x,
                                                 const float* __restrict__ W,
                                                 const float* __restrict__ b) {
    int idx = blockIdx.x * 256 + threadIdx.x;     // NN*128 threads
    int n = idx >> 7, c = idx & 127;
    const float* xr = x + n * 12;
    float acc = b[c];
#pragma unroll
    for (int k = 0; k < 12; k++) acc += xr[k] * W[k * HH + c];
    g_cat[(size_t)n * CATW + c] = acc;
}

// ---------------------------------------------------------------- edge kernel
// For each edge: e = edge_attr @ edge_W[l] + edge_b[l]; atomicAdd h[src]+e into agg[dst]
__global__ __launch_bounds__(256) void edge_k(const int* __restrict__ ei,
                                              const float* __restrict__ ea,
                                              const float* __restrict__ eW,
                                              const float* __restrict__ eb,
                                              int layer) {
    int lane = threadIdx.x & 31;
    int wid = (blockIdx.x * 256 + threadIdx.x) >> 5;
    int nwarp = (gridDim.x * 256) >> 5;
    int c0 = lane * 4;

    float w[3][4], bb[4];
#pragma unroll
    for (int j = 0; j < 3; j++)
#pragma unroll
        for (int i = 0; i < 4; i++) w[j][i] = eW[j * HH + c0 + i];
#pragma unroll
    for (int i = 0; i < 4; i++) bb[i] = eb[c0 + i];

    const float* hbase = g_cat + layer * HH;

    for (int e = wid; e < EE; e += nwarp) {
        int src = ei[e];
        int dst = ei[EE + e];
        float a0 = ea[e * 3 + 0];
        float a1 = ea[e * 3 + 1];
        float a2 = ea[e * 3 + 2];
        float4 hv = *(const float4*)(hbase + (size_t)src * CATW + c0);
        float v0 = hv.x + a0 * w[0][0] + a1 * w[1][0] + a2 * w[2][0] + bb[0];
        float v1 = hv.y + a0 * w[0][1] + a1 * w[1][1] + a2 * w[2][1] + bb[1];
        float v2 = hv.z + a0 * w[0][2] + a1 * w[1][2] + a2 * w[2][2] + bb[2];
        float v3 = hv.w + a0 * w[0][3] + a1 * w[1][3] + a2 * w[2][3] + bb[3];
        float* ap = &g_agg[(size_t)dst * HH + c0];
        atomicAdd(ap + 0, v0);
        atomicAdd(ap + 1, v1);
        atomicAdd(ap + 2, v2);
        atomicAdd(ap + 3, v3);
    }
}

// ---------------------------------------------------------------- fused GIN MLP
// per 16-node tile: z=(1+eps)h+agg ; t1=relu(bn1(z@W1+b1)) ; z2=relu(bn2(t1@W2+b2))
// h_new = LN(z2+h)  -> written to layer+1 slice of g_cat
__global__ __launch_bounds__(256) void mlp_k(const float* __restrict__ W1, const float* __restrict__ b1,
                                             const float* __restrict__ g1, const float* __restrict__ bb1,
                                             const float* __restrict__ rm1, const float* __restrict__ rv1,
                                             const float* __restrict__ W2, const float* __restrict__ b2,
                                             const float* __restrict__ g2, const float* __restrict__ bb2,
                                             const float* __restrict__ rm2, const float* __restrict__ rv2,
                                             const float* __restrict__ epsp,
                                             const float* __restrict__ lng, const float* __restrict__ lnb,
                                             int layer) {
    __shared__ float zs[16 * 128];   // 8KB  (z, later reused for residual result)
    __shared__ float t1[16 * 256];   // 16KB
    int tid = threadIdx.x;
    int n0 = blockIdx.x * 16;
    float epsv = epsp[layer];

    // stage A: build z tile
#pragma unroll
    for (int i = 0; i < 8; i++) {
        int idx = tid + i * 256;
        int m = idx >> 7, c = idx & 127;
        int n = n0 + m;
        float hv = g_cat[(size_t)n * CATW + layer * HH + c];
        zs[idx] = (1.f + epsv) * hv + g_agg[(size_t)n * HH + c];
    }
    __syncthreads();

    // stage B: t1[m][c] = relu(bn1(z @ W1 + b1)), c = tid (0..255)
    {
        int c = tid;
        float s = g1[c] * rsqrtf(rv1[c] + 1e-5f);
        float t = bb1[c] - rm1[c] * s;
        float base = b1[c];
        float acc[16];
#pragma unroll
        for (int m = 0; m < 16; m++) acc[m] = 0.f;
        const float4* z4 = (const float4*)zs;
        for (int k = 0; k < 128; k += 4) {
            float w0 = W1[(k + 0) * 256 + c];
            float w1 = W1[(k + 1) * 256 + c];
            float w2 = W1[(k + 2) * 256 + c];
            float w3 = W1[(k + 3) * 256 + c];
#pragma unroll
            for (int m = 0; m < 16; m++) {
                float4 z = z4[m * 32 + (k >> 2)];
                acc[m] += z.x * w0 + z.y * w1 + z.z * w2 + z.w * w3;
            }
        }
#pragma unroll
        for (int m = 0; m < 16; m++) {
            float v = (acc[m] + base) * s + t;
            t1[m * 256 + c] = fmaxf(v, 0.f);
        }
    }
    __syncthreads();

    // stage C: z2 = relu(bn2(t1 @ W2 + b2)) + h  -> zs (reused)
    {
        int c = tid & 127;
        int mg = tid >> 7;  // 0,1 -> rows mg*8..mg*8+7
        float s = g2[c] * rsqrtf(rv2[c] + 1e-5f);
        float t = bb2[c] - rm2[c] * s;
        float base = b2[c];
        float acc[8];
#pragma unroll
        for (int m = 0; m < 8; m++) acc[m] = 0.f;
        const float4* t14 = (const float4*)t1;
        for (int k = 0; k < 256; k += 4) {
            float w0 = W2[(k + 0) * 128 + c];
            float w1 = W2[(k + 1) * 128 + c];
            float w2 = W2[(k + 2) * 128 + c];
            float w3 = W2[(k + 3) * 128 + c];
#pragma unroll
            for (int m = 0; m < 8; m++) {
                int row = mg * 8 + m;
                float4 z = t14[row * 64 + (k >> 2)];
                acc[m] += z.x * w0 + z.y * w1 + z.z * w2 + z.w * w3;
            }
        }
#pragma unroll
        for (int m = 0; m < 8; m++) {
            int row = mg * 8 + m;
            int n = n0 + row;
            float v = fmaxf((acc[m] + base) * s + t, 0.f);
            v += g_cat[(size_t)n * CATW + layer * HH + c];
            zs[row * 128 + c] = v;
        }
    }
    __syncthreads();

    // stage D: LayerNorm each row, write to layer+1 slice
    {
        int w = tid >> 5, lane = tid & 31;
#pragma unroll
        for (int r = 0; r < 2; r++) {
            int m = w * 2 + r;
            float4 v = ((const float4*)zs)[m * 32 + lane];
            float sum = v.x + v.y + v.z + v.w;
            float sq = v.x * v.x + v.y * v.y + v.z * v.z + v.w * v.w;
#pragma unroll
            for (int o = 16; o; o >>= 1) {
                sum += __shfl_xor_sync(0xffffffffu, sum, o);
                sq  += __shfl_xor_sync(0xffffffffu, sq, o);
            }
            float mu = sum * (1.f / 128.f);
            float var = sq * (1.f / 128.f) - mu * mu;
            float inv = rsqrtf(var + 1e-5f);
            int n = n0 + m;
            int c0 = lane * 4;
            float4 o;
            o.x = (v.x - mu) * inv * lng[c0 + 0] + lnb[c0 + 0];
            o.y = (v.y - mu) * inv * lng[c0 + 1] + lnb[c0 + 1];
            o.z = (v.z - mu) * inv * lng[c0 + 2] + lnb[c0 + 2];
            o.w = (v.w - mu) * inv * lng[c0 + 3] + lnb[c0 + 3];
            *(float4*)&g_cat[(size_t)n * CATW + (layer + 1) * HH + c0] = o;
        }
    }
}

// ---------------------------------------------------------------- graph counts
__global__ __launch_bounds__(256) void count_k(const int* __restrict__ batch) {
    __shared__ int sc[BB];
    int tid = threadIdx.x;
    if (tid < BB) sc[tid] = 0;
    __syncthreads();
    int n = blockIdx.x * 256 + tid;
    if (n < NN) atomicAdd(&sc[batch[n]], 1);
    __syncthreads();
    if (tid < BB) atomicAdd(&g_cnt[tid], sc[tid]);
}

// ---------------------------------------------------------------- output head
// node_emb = relu(cat @ oW1 + ob1) @ oW2 + ob2 ; also accumulate pool sums
__global__ __launch_bounds__(256) void out_k(const float* __restrict__ oW1, const float* __restrict__ ob1,
                                             const float* __restrict__ oW2, const float* __restrict__ ob2,
                                             const int* __restrict__ batch,
                                             float* __restrict__ out) {
    __shared__ float cs[16 * 512];   // 32KB
    __shared__ float t1[16 * 128];   // 8KB
    int tid = threadIdx.x;
    int n0 = blockIdx.x * 16;

    // load cat tile (16 consecutive rows are contiguous)
    {
        const float4* src = (const float4*)g_cat + (size_t)n0 * (CATW / 4);
        float4* dst = (float4*)cs;
#pragma unroll
        for (int i = 0; i < 8; i++) {
            int idx = tid + i * 256;     // 2048 float4
            dst[idx] = src[idx];
        }
    }
    __syncthreads();

    int c = tid & 127;
    int mg = tid >> 7;

    // GEMM1: K=512
    {
        float acc[8];
#pragma unroll
        for (int m = 0; m < 8; m++) acc[m] = 0.f;
        const float4* c4 = (const float4*)cs;
        for (int k = 0; k < 512; k += 4) {
            float w0 = oW1[(k + 0) * 128 + c];
            float w1 = oW1[(k + 1) * 128 + c];
            float w2 = oW1[(k + 2) * 128 + c];
            float w3 = oW1[(k + 3) * 128 + c];
#pragma unroll
            for (int m = 0; m < 8; m++) {
                int row = mg * 8 + m;
                float4 z = c4[row * 128 + (k >> 2)];
                acc[m] += z.x * w0 + z.y * w1 + z.z * w2 + z.w * w3;
            }
        }
        float base = ob1[c];
#pragma unroll
        for (int m = 0; m < 8; m++) {
            int row = mg * 8 + m;
            t1[row * 128 + c] = fmaxf(acc[m] + base, 0.f);
        }
    }
    __syncthreads();

    // GEMM2: K=128, write node_emb + pool atomics
    {
        float acc[8];
#pragma unroll
        for (int m = 0; m < 8; m++) acc[m] = 0.f;
        const float4* t4 = (const float4*)t1;
        for (int k = 0; k < 128; k += 4) {
            float w0 = oW2[(k + 0) * 128 + c];
            float w1 = oW2[(k + 1) * 128 + c];
            float w2 = oW2[(k + 2) * 128 + c];
            float w3 = oW2[(k + 3) * 128 + c];
#pragma unroll
            for (int m = 0; m < 8; m++) {
                int row = mg * 8 + m;
                float4 z = t4[row * 32 + (k >> 2)];
                acc[m] += z.x * w0 + z.y * w1 + z.z * w2 + z.w * w3;
            }
        }
        float base = ob2[c];
#pragma unroll
        for (int m = 0; m < 8; m++) {
            int row = mg * 8 + m;
            int n = n0 + row;
            float v = acc[m] + base;
            out[(size_t)n * HH + c] = v;
            atomicAdd(&g_pool[batch[n] * HH + c], v);
        }
    }
}

// ---------------------------------------------------------------- pool divide
__global__ __launch_bounds__(256) void pooldiv_k(float* __restrict__ out) {
    int i = blockIdx.x * 256 + threadIdx.x;
    if (i < BB * HH) {
        int b = i >> 7;
        float c = (float)g_cnt[b];
        out[(size_t)NN * HH + i] = g_pool[i] / fmaxf(c, 1.f);
    }
}

// ---------------------------------------------------------------- launch
extern "C" void kernel_launch(void* const* d_in, const int* in_sizes, int n_in,
                              void* d_out, int out_size) {
    const float* x        = (const float*)d_in[0];
    const int*   ei       = (const int*)d_in[1];
    const float* ea       = (const float*)d_in[2];
    const int*   batch    = (const int*)d_in[3];
    const float* in_W     = (const float*)d_in[4];
    const float* in_b     = (const float*)d_in[5];
    const float* edge_W   = (const float*)d_in[6];
    const float* edge_b   = (const float*)d_in[7];
    const float* mlp_W1   = (const float*)d_in[8];
    const float* mlp_b1   = (const float*)d_in[9];
    const float* bn1_g    = (const float*)d_in[10];
    const float* bn1_b    = (const float*)d_in[11];
    const float* bn1_rm   = (const float*)d_in[12];
    const float* bn1_rv   = (const float*)d_in[13];
    const float* mlp_W2   = (const float*)d_in[14];
    const float* mlp_b2   = (const float*)d_in[15];
    const float* bn2_g    = (const float*)d_in[16];
    const float* bn2_b    = (const float*)d_in[17];
    const float* bn2_rm   = (const float*)d_in[18];
    const float* bn2_rv   = (const float*)d_in[19];
    const float* epsp     = (const float*)d_in[20];
    const float* ln_g     = (const float*)d_in[21];
    const float* ln_b     = (const float*)d_in[22];
    const float* out_W1   = (const float*)d_in[23];
    const float* out_b1   = (const float*)d_in[24];
    const float* out_W2   = (const float*)d_in[25];
    const float* out_b2   = (const float*)d_in[26];
    float* out = (float*)d_out;

    in_proj_k<<<NN * HH / 256, 256>>>(x, in_W, in_b);

    for (int l = 0; l < LL; l++) {
        zero_agg_k<<<NN * HH / 4 / 256, 256>>>();
        edge_k<<<1184, 256>>>(ei, ea, edge_W + l * 3 * HH, edge_b + l * HH, l);
        mlp_k<<<NN / 16, 256>>>(mlp_W1 + l * HH * 256, mlp_b1 + l * 256,
                                bn1_g + l * 256, bn1_b + l * 256, bn1_rm + l * 256, bn1_rv + l * 256,
                                mlp_W2 + l * 256 * HH, mlp_b2 + l * HH,
                                bn2_g + l * HH, bn2_b + l * HH, bn2_rm + l * HH, bn2_rv + l * HH,
                                epsp, ln_g + l * HH, ln_b + l * HH, l);
    }

    zero_pool_k<<<8, 256>>>();
    count_k<<<(NN + 255) / 256, 256>>>(batch);
    out_k<<<NN / 16, 256>>>(out_W1, out_b1, out_W2, out_b2, batch, out);
    pooldiv_k<<<8, 256>>>(out);
}

// round 4
// speedup vs baseline: 1.3508x; 1.3508x over previous
#include <cuda_runtime.h>
#include <cuda_bf16.h>

#define NN 100000
#define EE 600000
#define HH 128
#define LL 3
#define BB 16
#define CATW 512   // (LL+1)*HH

// ---- scratch (device globals: no allocation allowed) ----
__device__ float g_cat[(size_t)NN * CATW];   // all_h concatenated [N, 4*128]
__device__ int   g_deg[NN];
__device__ int   g_start[NN + 1];
__device__ int   g_cursor[NN];
__device__ int   g_srcs[EE];                 // src ids sorted by dst
__device__ float g_eagg[NN * 4];             // sum of edge_attr per dst (3 used)
__device__ float g_pool[BB * HH];
__device__ int   g_cnt[BB];
// split-bf16 packed weights: uint2 {hi_pair(k,k+1), lo_pair}
__device__ uint2 g_W1p[LL * 64 * 256];       // [l][k2=64][n=256]
__device__ uint2 g_W2p[LL * 128 * 128];      // [l][k2=128][n=128]
__device__ uint2 g_oW1p[256 * 128];          // [k2=256][n=128]
__device__ uint2 g_oW2p[64 * 128];           // [k2=64][n=128]
// folded BN: v = acc*a + b
__device__ float g_c1a[LL * 256], g_c1b[LL * 256];
__device__ float g_c2a[LL * 128], g_c2b[LL * 128];

// ---------------------------------------------------------------- helpers
__device__ __forceinline__ uint2 splitpack2(float x0, float x1) {
    __nv_bfloat16 h0 = __float2bfloat16(x0);
    __nv_bfloat16 h1 = __float2bfloat16(x1);
    float r0 = x0 - __bfloat162float(h0);
    float r1 = x1 - __bfloat162float(h1);
    __nv_bfloat16 l0 = __float2bfloat16(r0);
    __nv_bfloat16 l1 = __float2bfloat16(r1);
    unsigned hu = (unsigned)__bfloat16_as_ushort(h0) | ((unsigned)__bfloat16_as_ushort(h1) << 16);
    unsigned lu = (unsigned)__bfloat16_as_ushort(l0) | ((unsigned)__bfloat16_as_ushort(l1) << 16);
    return make_uint2(hu, lu);
}

__device__ __forceinline__ void mma_bf16(float& c0, float& c1, float& c2, float& c3,
                                         unsigned a0, unsigned a1, unsigned a2, unsigned a3,
                                         unsigned b0, unsigned b1) {
    asm volatile("mma.sync.aligned.m16n8k16.row.col.f32.bf16.bf16.f32 "
                 "{%0,%1,%2,%3},{%4,%5,%6,%7},{%8,%9},{%0,%1,%2,%3};\n"
                 : "+f"(c0), "+f"(c1), "+f"(c2), "+f"(c3)
                 : "r"(a0), "r"(a1), "r"(a2), "r"(a3), "r"(b0), "r"(b1));
}

// ---------------------------------------------------------------- misc zero
__global__ __launch_bounds__(256) void zero_misc_k() {
    int i = blockIdx.x * 256 + threadIdx.x;
    if (i < NN) {
        g_deg[i] = 0;
        ((float4*)g_eagg)[i] = make_float4(0.f, 0.f, 0.f, 0.f);
    }
    if (i < BB * HH) g_pool[i] = 0.f;
    if (i < BB) g_cnt[i] = 0;
}

// ---------------------------------------------------------------- degree + edge-attr agg
__global__ __launch_bounds__(256) void deg_eagg_k(const int* __restrict__ ei,
                                                  const float* __restrict__ ea) {
    int e = blockIdx.x * 256 + threadIdx.x;
    if (e >= EE) return;
    int dst = ei[EE + e];
    atomicAdd(&g_deg[dst], 1);
    atomicAdd(&g_eagg[dst * 4 + 0], ea[e * 3 + 0]);
    atomicAdd(&g_eagg[dst * 4 + 1], ea[e * 3 + 1]);
    atomicAdd(&g_eagg[dst * 4 + 2], ea[e * 3 + 2]);
}

// ---------------------------------------------------------------- one-block scan
__global__ __launch_bounds__(1024) void scan_k() {
    __shared__ int sums[1024];
    int tid = threadIdx.x;
    const int CH = (NN + 1023) / 1024;   // 98
    int base = tid * CH;
    int s = 0;
    for (int i = 0; i < CH; i++) {
        int n = base + i;
        if (n < NN) s += g_deg[n];
    }
    sums[tid] = s;
    __syncthreads();
    for (int off = 1; off < 1024; off <<= 1) {
        int v = sums[tid];
        int add = (tid >= off) ? sums[tid - off] : 0;
        __syncthreads();
        sums[tid] = v + add;
        __syncthreads();
    }
    int run = sums[tid] - s;   // exclusive prefix at chunk start
    for (int i = 0; i < CH; i++) {
        int n = base + i;
        if (n < NN) {
            g_start[n] = run;
            g_cursor[n] = run;
            run += g_deg[n];
        }
    }
    if (tid == 0) g_start[NN] = EE;
}

// ---------------------------------------------------------------- edge reorder (CSR by dst)
__global__ __launch_bounds__(256) void reorder_k(const int* __restrict__ ei) {
    int e = blockIdx.x * 256 + threadIdx.x;
    if (e >= EE) return;
    int dst = ei[EE + e];
    int pos = atomicAdd(&g_cursor[dst], 1);
    g_srcs[pos] = ei[e];
}

// ---------------------------------------------------------------- weight pack (split bf16)
__global__ __launch_bounds__(256) void pack_all_k(const float* __restrict__ mW1,
                                                  const float* __restrict__ mW2,
                                                  const float* __restrict__ oW1,
                                                  const float* __restrict__ oW2) {
    int idx = blockIdx.x * 256 + threadIdx.x;
    // region A: W1p  3 * 64 * 256 = 49152
    if (idx < 49152) {
        int l = idx / 16384, r = idx % 16384;
        int k2 = r / 256, n = r % 256;
        const float* src = mW1 + l * (128 * 256);
        g_W1p[idx] = splitpack2(src[(2 * k2) * 256 + n], src[(2 * k2 + 1) * 256 + n]);
        return;
    }
    int j = idx - 49152;
    // region B: W2p  3 * 128 * 128 = 49152
    if (j < 49152) {
        int l = j / 16384, r = j % 16384;
        int k2 = r / 128, n = r % 128;
        const float* src = mW2 + l * (256 * 128);
        g_W2p[j] = splitpack2(src[(2 * k2) * 128 + n], src[(2 * k2 + 1) * 128 + n]);
        return;
    }
    j -= 49152;
    // region C: oW1p 256 * 128 = 32768
    if (j < 32768) {
        int k2 = j / 128, n = j % 128;
        g_oW1p[j] = splitpack2(oW1[(2 * k2) * 128 + n], oW1[(2 * k2 + 1) * 128 + n]);
        return;
    }
    j -= 32768;
    // region D: oW2p 64 * 128 = 8192
    if (j < 8192) {
        int k2 = j / 128, n = j % 128;
        g_oW2p[j] = splitpack2(oW2[(2 * k2) * 128 + n], oW2[(2 * k2 + 1) * 128 + n]);
    }
}

// ---------------------------------------------------------------- BN fold
__global__ __launch_bounds__(256) void bnprep_k(const float* __restrict__ b1, const float* __restrict__ g1,
                                                const float* __restrict__ bb1, const float* __restrict__ rm1,
                                                const float* __restrict__ rv1,
                                                const float* __restrict__ b2, const float* __restrict__ g2,
                                                const float* __restrict__ bb2, const float* __restrict__ rm2,
                                                const float* __restrict__ rv2) {
    int i = blockIdx.x * 256 + threadIdx.x;
    if (i < LL * 256) {
        float s = g1[i] * rsqrtf(rv1[i] + 1e-5f);
        g_c1a[i] = s;
        g_c1b[i] = (b1[i] - rm1[i]) * s + bb1[i];
    }
    if (i < LL * 128) {
        float s = g2[i] * rsqrtf(rv2[i] + 1e-5f);
        g_c2a[i] = s;
        g_c2b[i] = (b2[i] - rm2[i]) * s + bb2[i];
    }
}

// ---------------------------------------------------------------- input proj
__global__ __launch_bounds__(256) void in_proj_k(const float* __restrict__ x,
                                                 const float* __restrict__ W,
                                                 const float* __restrict__ b) {
    int idx = blockIdx.x * 256 + threadIdx.x;
    int n = idx >> 7, c = idx & 127;
    const float* xr = x + n * 12;
    float acc = b[c];
#pragma unroll
    for (int k = 0; k < 12; k++) acc += xr[k] * W[k * HH + c];
    g_cat[(size_t)n * CATW + c] = acc;
}

// ---------------------------------------------------------------- fused GIN layer (tensor core)
// block = 32 nodes, 256 threads (8 warps)
// dynamic smem: zsp uint2[32][66] (16896B) | t1p uint2[32][130] (33280B) = 50176B
__global__ __launch_bounds__(256) void mlp_k(const float* __restrict__ eW,
                                             const float* __restrict__ ebias,
                                             const float* __restrict__ epsp,
                                             const float* __restrict__ lng,
                                             const float* __restrict__ lnb,
                                             int layer) {
    extern __shared__ unsigned char sm_raw[];
    uint2* zsp = (uint2*)sm_raw;                       // [32][66]
    uint2* t1p = (uint2*)(sm_raw + 16896);             // [32][130]
    float* zsf = (float*)sm_raw;                       // alias: [32][132] floats

    int tid = threadIdx.x;
    int w = tid >> 5, lane = tid & 31;
    int g = lane >> 2, tig = lane & 3;
    int n0 = blockIdx.x * 32;
    float eps1 = 1.f + epsp[layer];

    // ---- stage A: z = (1+eps)h + sum_src h[src] + eagg@W_e + deg*b_e  -> split-packed zsp
    {
        int c0 = lane * 4;
        float4 ew0 = *(const float4*)&eW[0 * HH + c0];
        float4 ew1 = *(const float4*)&eW[1 * HH + c0];
        float4 ew2 = *(const float4*)&eW[2 * HH + c0];
        float4 eb4 = *(const float4*)&ebias[c0];
#pragma unroll
        for (int r = 0; r < 4; r++) {
            int n = n0 + w * 4 + r;
            const float* hr = g_cat + (size_t)n * CATW + layer * HH + c0;
            float4 h4 = *(const float4*)hr;
            float e0 = g_eagg[n * 4 + 0], e1 = g_eagg[n * 4 + 1], e2 = g_eagg[n * 4 + 2];
            int s0 = g_start[n], s1 = g_start[n + 1];
            float dg = (float)(s1 - s0);
            float4 acc;
            acc.x = eps1 * h4.x + e0 * ew0.x + e1 * ew1.x + e2 * ew2.x + dg * eb4.x;
            acc.y = eps1 * h4.y + e0 * ew0.y + e1 * ew1.y + e2 * ew2.y + dg * eb4.y;
            acc.z = eps1 * h4.z + e0 * ew0.z + e1 * ew1.z + e2 * ew2.z + dg * eb4.z;
            acc.w = eps1 * h4.w + e0 * ew0.w + e1 * ew1.w + e2 * ew2.w + dg * eb4.w;
            for (int e = s0; e < s1; e++) {
                int src = g_srcs[e];
                float4 v = *(const float4*)(g_cat + (size_t)src * CATW + layer * HH + c0);
                acc.x += v.x; acc.y += v.y; acc.z += v.z; acc.w += v.w;
            }
            uint2 p0 = splitpack2(acc.x, acc.y);
            uint2 p1 = splitpack2(acc.z, acc.w);
            ((uint4*)zsp)[(w * 4 + r) * 33 + lane] = make_uint4(p0.x, p0.y, p1.x, p1.y);
        }
    }
    __syncthreads();

    // ---- GEMM1: [32x128] @ [128x256] -> bn1 relu -> t1p
    {
        int wm = w & 1, wn = w >> 1;
        int rowA = wm * 16, nb = wn * 64;
        const uint2* Wp = g_W1p + layer * (64 * 256);
        float c[8][4];
#pragma unroll
        for (int t = 0; t < 8; t++) { c[t][0] = c[t][1] = c[t][2] = c[t][3] = 0.f; }
#pragma unroll 2
        for (int kb2 = 0; kb2 < 64; kb2 += 8) {
            uint2 r0 = zsp[(rowA + g) * 66 + kb2 + tig];
            uint2 r1 = zsp[(rowA + g + 8) * 66 + kb2 + tig];
            uint2 r2 = zsp[(rowA + g) * 66 + kb2 + 4 + tig];
            uint2 r3 = zsp[(rowA + g + 8) * 66 + kb2 + 4 + tig];
#pragma unroll
            for (int t = 0; t < 8; t++) {
                int n = nb + t * 8 + g;
                uint2 q0 = Wp[(kb2 + tig) * 256 + n];
                uint2 q1 = Wp[(kb2 + 4 + tig) * 256 + n];
                mma_bf16(c[t][0], c[t][1], c[t][2], c[t][3], r0.x, r1.x, r2.x, r3.x, q0.x, q1.x);
                mma_bf16(c[t][0], c[t][1], c[t][2], c[t][3], r0.x, r1.x, r2.x, r3.x, q0.y, q1.y);
                mma_bf16(c[t][0], c[t][1], c[t][2], c[t][3], r0.y, r1.y, r2.y, r3.y, q0.x, q1.x);
            }
        }
        const float* A1 = g_c1a + layer * 256;
        const float* B1 = g_c1b + layer * 256;
#pragma unroll
        for (int t = 0; t < 8; t++) {
            int col = nb + t * 8 + tig * 2;
            float a0 = A1[col], b0 = B1[col], a1 = A1[col + 1], b1 = B1[col + 1];
            float v00 = fmaxf(c[t][0] * a0 + b0, 0.f);
            float v01 = fmaxf(c[t][1] * a1 + b1, 0.f);
            float v10 = fmaxf(c[t][2] * a0 + b0, 0.f);
            float v11 = fmaxf(c[t][3] * a1 + b1, 0.f);
            int c2 = col >> 1;
            t1p[(rowA + g) * 130 + c2] = splitpack2(v00, v01);
            t1p[(rowA + g + 8) * 130 + c2] = splitpack2(v10, v11);
        }
    }
    __syncthreads();

    // ---- GEMM2: [32x256] @ [256x128] -> bn2 relu + residual h -> zsf
    {
        int wm = w & 1, wn = w >> 1;
        int rowA = wm * 16, nb = wn * 32;
        const uint2* Wp = g_W2p + layer * (128 * 128);
        float c[4][4];
#pragma unroll
        for (int t = 0; t < 4; t++) { c[t][0] = c[t][1] = c[t][2] = c[t][3] = 0.f; }
#pragma unroll 2
        for (int kb2 = 0; kb2 < 128; kb2 += 8) {
            uint2 r0 = t1p[(rowA + g) * 130 + kb2 + tig];
            uint2 r1 = t1p[(rowA + g + 8) * 130 + kb2 + tig];
            uint2 r2 = t1p[(rowA + g) * 130 + kb2 + 4 + tig];
            uint2 r3 = t1p[(rowA + g + 8) * 130 + kb2 + 4 + tig];
#pragma unroll
            for (int t = 0; t < 4; t++) {
                int n = nb + t * 8 + g;
                uint2 q0 = Wp[(kb2 + tig) * 128 + n];
                uint2 q1 = Wp[(kb2 + 4 + tig) * 128 + n];
                mma_bf16(c[t][0], c[t][1], c[t][2], c[t][3], r0.x, r1.x, r2.x, r3.x, q0.x, q1.x);
                mma_bf16(c[t][0], c[t][1], c[t][2], c[t][3], r0.x, r1.x, r2.x, r3.x, q0.y, q1.y);
                mma_bf16(c[t][0], c[t][1], c[t][2], c[t][3], r0.y, r1.y, r2.y, r3.y, q0.x, q1.x);
            }
        }
        const float* A2 = g_c2a + layer * 128;
        const float* B2 = g_c2b + layer * 128;
#pragma unroll
        for (int t = 0; t < 4; t++) {
            int col = nb + t * 8 + tig * 2;
            float a0 = A2[col], b0 = B2[col], a1 = A2[col + 1], b1 = B2[col + 1];
            int r0w = rowA + g, r1w = rowA + g + 8;
            const float* h0 = g_cat + (size_t)(n0 + r0w) * CATW + layer * HH + col;
            const float* h1 = g_cat + (size_t)(n0 + r1w) * CATW + layer * HH + col;
            float v00 = fmaxf(c[t][0] * a0 + b0, 0.f) + h0[0];
            float v01 = fmaxf(c[t][1] * a1 + b1, 0.f) + h0[1];
            float v10 = fmaxf(c[t][2] * a0 + b0, 0.f) + h1[0];
            float v11 = fmaxf(c[t][3] * a1 + b1, 0.f) + h1[1];
            zsf[r0w * 132 + col] = v00;
            zsf[r0w * 132 + col + 1] = v01;
            zsf[r1w * 132 + col] = v10;
            zsf[r1w * 132 + col + 1] = v11;
        }
    }
    __syncthreads();

    // ---- LayerNorm rows -> g_cat layer+1
    {
#pragma unroll
        for (int r = 0; r < 4; r++) {
            int m = w * 4 + r;
            float4 v = *(const float4*)&zsf[m * 132 + lane * 4];
            float sum = v.x + v.y + v.z + v.w;
            float sq = v.x * v.x + v.y * v.y + v.z * v.z + v.w * v.w;
#pragma unroll
            for (int o = 16; o; o >>= 1) {
                sum += __shfl_xor_sync(0xffffffffu, sum, o);
                sq += __shfl_xor_sync(0xffffffffu, sq, o);
            }
            float mu = sum * (1.f / 128.f);
            float var = sq * (1.f / 128.f) - mu * mu;
            float inv = rsqrtf(var + 1e-5f);
            int c0 = lane * 4;
            float4 o;
            o.x = (v.x - mu) * inv * lng[c0 + 0] + lnb[c0 + 0];
            o.y = (v.y - mu) * inv * lng[c0 + 1] + lnb[c0 + 1];
            o.z = (v.z - mu) * inv * lng[c0 + 2] + lnb[c0 + 2];
            o.w = (v.w - mu) * inv * lng[c0 + 3] + lnb[c0 + 3];
            *(float4*)&g_cat[(size_t)(n0 + m) * CATW + (layer + 1) * HH + c0] = o;
        }
    }
}

// ---------------------------------------------------------------- graph counts
__global__ __launch_bounds__(256) void count_k(const int* __restrict__ batch) {
    __shared__ int sc[BB];
    int tid = threadIdx.x;
    if (tid < BB) sc[tid] = 0;
    __syncthreads();
    int n = blockIdx.x * 256 + tid;
    if (n < NN) atomicAdd(&sc[batch[n]], 1);
    __syncthreads();
    if (tid < BB) atomicAdd(&g_cnt[tid], sc[tid]);
}

// ---------------------------------------------------------------- output head (tensor core)
// block = 32 nodes; dynamic smem: catp uint2[32][258] (66048B) | t1p uint2[32][66] (16896B) = 82944B
__global__ __launch_bounds__(256) void out_k(const float* __restrict__ ob1,
                                             const float* __restrict__ ob2,
                                             const int* __restrict__ batch,
                                             float* __restrict__ out) {
    extern __shared__ unsigned char sm_raw[];
    uint2* catp = (uint2*)sm_raw;                     // [32][258]
    uint2* t1p = (uint2*)(sm_raw + 66048);            // [32][66]

    int tid = threadIdx.x;
    int w = tid >> 5, lane = tid & 31;
    int g = lane >> 2, tig = lane & 3;
    int n0 = blockIdx.x * 32;

    // stage: split-pack the 32x512 cat tile
#pragma unroll
    for (int i = 0; i < 16; i++) {
        int idx = tid + i * 256;          // 0..4095  (32 rows x 128 float4)
        int n = idx >> 7, c4 = idx & 127;
        float4 v = *(const float4*)(g_cat + (size_t)(n0 + n) * CATW + c4 * 4);
        uint2 p0 = splitpack2(v.x, v.y);
        uint2 p1 = splitpack2(v.z, v.w);
        ((uint4*)catp)[n * 129 + c4] = make_uint4(p0.x, p0.y, p1.x, p1.y);
    }
    __syncthreads();

    int wm = w & 1, wn = w >> 1;
    int rowA = wm * 16, nb = wn * 32;

    // GEMM1: [32x512] @ [512x128] -> relu -> t1p
    {
        float c[4][4];
#pragma unroll
        for (int t = 0; t < 4; t++) { c[t][0] = c[t][1] = c[t][2] = c[t][3] = 0.f; }
#pragma unroll 4
        for (int kb2 = 0; kb2 < 256; kb2 += 8) {
            uint2 r0 = catp[(rowA + g) * 258 + kb2 + tig];
            uint2 r1 = catp[(rowA + g + 8) * 258 + kb2 + tig];
            uint2 r2 = catp[(rowA + g) * 258 + kb2 + 4 + tig];
            uint2 r3 = catp[(rowA + g + 8) * 258 + kb2 + 4 + tig];
#pragma unroll
            for (int t = 0; t < 4; t++) {
                int n = nb + t * 8 + g;
                uint2 q0 = g_oW1p[(kb2 + tig) * 128 + n];
                uint2 q1 = g_oW1p[(kb2 + 4 + tig) * 128 + n];
                mma_bf16(c[t][0], c[t][1], c[t][2], c[t][3], r0.x, r1.x, r2.x, r3.x, q0.x, q1.x);
                mma_bf16(c[t][0], c[t][1], c[t][2], c[t][3], r0.x, r1.x, r2.x, r3.x, q0.y, q1.y);
                mma_bf16(c[t][0], c[t][1], c[t][2], c[t][3], r0.y, r1.y, r2.y, r3.y, q0.x, q1.x);
            }
        }
#pragma unroll
        for (int t = 0; t < 4; t++) {
            int col = nb + t * 8 + tig * 2;
            float b0 = ob1[col], b1 = ob1[col + 1];
            float v00 = fmaxf(c[t][0] + b0, 0.f);
            float v01 = fmaxf(c[t][1] + b1, 0.f);
            float v10 = fmaxf(c[t][2] + b0, 0.f);
            float v11 = fmaxf(c[t][3] + b1, 0.f);
            int c2 = col >> 1;
            t1p[(rowA + g) * 66 + c2] = splitpack2(v00, v01);
            t1p[(rowA + g + 8) * 66 + c2] = splitpack2(v10, v11);
        }
    }
    __syncthreads();

    // GEMM2: [32x128] @ [128x128] -> out + pool
    {
        float c[4][4];
#pragma unroll
        for (int t = 0; t < 4; t++) { c[t][0] = c[t][1] = c[t][2] = c[t][3] = 0.f; }
#pragma unroll 2
        for (int kb2 = 0; kb2 < 64; kb2 += 8) {
            uint2 r0 = t1p[(rowA + g) * 66 + kb2 + tig];
            uint2 r1 = t1p[(rowA + g + 8) * 66 + kb2 + tig];
            uint2 r2 = t1p[(rowA + g) * 66 + kb2 + 4 + tig];
            uint2 r3 = t1p[(rowA + g + 8) * 66 + kb2 + 4 + tig];
#pragma unroll
            for (int t = 0; t < 4; t++) {
                int n = nb + t * 8 + g;
                uint2 q0 = g_oW2p[(kb2 + tig) * 128 + n];
                uint2 q1 = g_oW2p[(kb2 + 4 + tig) * 128 + n];
                mma_bf16(c[t][0], c[t][1], c[t][2], c[t][3], r0.x, r1.x, r2.x, r3.x, q0.x, q1.x);
                mma_bf16(c[t][0], c[t][1], c[t][2], c[t][3], r0.x, r1.x, r2.x, r3.x, q0.y, q1.y);
                mma_bf16(c[t][0], c[t][1], c[t][2], c[t][3], r0.y, r1.y, r2.y, r3.y, q0.x, q1.x);
            }
        }
        int nA = n0 + rowA + g;
        int nB = nA + 8;
        int bA = batch[nA], bB = batch[nB];
#pragma unroll
        for (int t = 0; t < 4; t++) {
            int col = nb + t * 8 + tig * 2;
            float b0 = ob2[col], b1 = ob2[col + 1];
            float v00 = c[t][0] + b0, v01 = c[t][1] + b1;
            float v10 = c[t][2] + b0, v11 = c[t][3] + b1;
            out[(size_t)nA * HH + col] = v00;
            out[(size_t)nA * HH + col + 1] = v01;
            out[(size_t)nB * HH + col] = v10;
            out[(size_t)nB * HH + col + 1] = v11;
            atomicAdd(&g_pool[bA * HH + col], v00);
            atomicAdd(&g_pool[bA * HH + col + 1], v01);
            atomicAdd(&g_pool[bB * HH + col], v10);
            atomicAdd(&g_pool[bB * HH + col + 1], v11);
        }
    }
}

// ---------------------------------------------------------------- pool divide
__global__ __launch_bounds__(256) void pooldiv_k(float* __restrict__ out) {
    int i = blockIdx.x * 256 + threadIdx.x;
    if (i < BB * HH) {
        int b = i >> 7;
        float c = (float)g_cnt[b];
        out[(size_t)NN * HH + i] = g_pool[i] / fmaxf(c, 1.f);
    }
}

// ---------------------------------------------------------------- launch
extern "C" void kernel_launch(void* const* d_in, const int* in_sizes, int n_in,
                              void* d_out, int out_size) {
    const float* x      = (const float*)d_in[0];
    const int*   ei     = (const int*)d_in[1];
    const float* ea     = (const float*)d_in[2];
    const int*   batch  = (const int*)d_in[3];
    const float* in_W   = (const float*)d_in[4];
    const float* in_b   = (const float*)d_in[5];
    const float* edge_W = (const float*)d_in[6];
    const float* edge_b = (const float*)d_in[7];
    const float* mlp_W1 = (const float*)d_in[8];
    const float* mlp_b1 = (const float*)d_in[9];
    const float* bn1_g  = (const float*)d_in[10];
    const float* bn1_b  = (const float*)d_in[11];
    const float* bn1_rm = (const float*)d_in[12];
    const float* bn1_rv = (const float*)d_in[13];
    const float* mlp_W2 = (const float*)d_in[14];
    const float* mlp_b2 = (const float*)d_in[15];
    const float* bn2_g  = (const float*)d_in[16];
    const float* bn2_b  = (const float*)d_in[17];
    const float* bn2_rm = (const float*)d_in[18];
    const float* bn2_rv = (const float*)d_in[19];
    const float* epsp   = (const float*)d_in[20];
    const float* ln_g   = (const float*)d_in[21];
    const float* ln_b   = (const float*)d_in[22];
    const float* out_W1 = (const float*)d_in[23];
    const float* out_b1 = (const float*)d_in[24];
    const float* out_W2 = (const float*)d_in[25];
    const float* out_b2 = (const float*)d_in[26];
    float* out = (float*)d_out;

    cudaFuncSetAttribute(mlp_k, cudaFuncAttributeMaxDynamicSharedMemorySize, 50176);
    cudaFuncSetAttribute(out_k, cudaFuncAttributeMaxDynamicSharedMemorySize, 82944);

    // preprocessing (recomputed every call; all cheap)
    zero_misc_k<<<(NN + 255) / 256, 256>>>();
    deg_eagg_k<<<(EE + 255) / 256, 256>>>(ei, ea);
    scan_k<<<1, 1024>>>();
    reorder_k<<<(EE + 255) / 256, 256>>>(ei);
    pack_all_k<<<(139264 + 255) / 256, 256>>>(mlp_W1, mlp_W2, out_W1, out_W2);
    bnprep_k<<<3, 256>>>(mlp_b1, bn1_g, bn1_b, bn1_rm, bn1_rv,
                         mlp_b2, bn2_g, bn2_b, bn2_rm, bn2_rv);

    in_proj_k<<<NN * HH / 256, 256>>>(x, in_W, in_b);
    count_k<<<(NN + 255) / 256, 256>>>(batch);

    for (int l = 0; l < LL; l++) {
        mlp_k<<<NN / 32, 256, 50176>>>(edge_W + l * 3 * HH, edge_b + l * HH,
                                       epsp, ln_g + l * HH, ln_b + l * HH, l);
    }

    out_k<<<NN / 32, 256, 82944>>>(out_b1, out_b2, batch, out);
    pooldiv_k<<<8, 256>>>(out);
}

// round 9
// speedup vs baseline: 1.4998x; 1.1103x over previous
#include <cuda_runtime.h>
#include <cuda_bf16.h>

#define NN 100000
#define EE 600000
#define HH 128
#define LL 3
#define BB 16
#define CATW 512   // (LL+1)*HH
#define NPAD 64    // tail padding rows

// ---- scratch (device globals: no allocation allowed) ----
__device__ float g_cat[(size_t)(NN + NPAD) * CATW];
__device__ int   g_deg[NN];
__device__ int   g_start[NN + 1];
__device__ int   g_cursor[NN];
__device__ int   g_srcs[EE];
__device__ float g_eagg[(NN + NPAD) * 4];
__device__ float g_pool[BB * HH];
__device__ int   g_cnt[BB];
// split-bf16 packed weights: uint2 {hi_pair(k,k+1), lo_pair}
__device__ uint2 g_W1p[LL * 64 * 256];
__device__ uint2 g_W2p[LL * 128 * 128];
__device__ uint2 g_oW1p[256 * 128];
__device__ uint2 g_oW2p[64 * 128];
// folded BN: v = acc*a + b
__device__ float g_c1a[LL * 256], g_c1b[LL * 256];
__device__ float g_c2a[LL * 128], g_c2b[LL * 128];

// ---------------------------------------------------------------- helpers
__device__ __forceinline__ uint2 splitpack2(float x0, float x1) {
    __nv_bfloat16 h0 = __float2bfloat16(x0);
    __nv_bfloat16 h1 = __float2bfloat16(x1);
    float r0 = x0 - __bfloat162float(h0);
    float r1 = x1 - __bfloat162float(h1);
    __nv_bfloat16 l0 = __float2bfloat16(r0);
    __nv_bfloat16 l1 = __float2bfloat16(r1);
    unsigned hu = (unsigned)__bfloat16_as_ushort(h0) | ((unsigned)__bfloat16_as_ushort(h1) << 16);
    unsigned lu = (unsigned)__bfloat16_as_ushort(l0) | ((unsigned)__bfloat16_as_ushort(l1) << 16);
    return make_uint2(hu, lu);
}

__device__ __forceinline__ void mma_bf16(float& c0, float& c1, float& c2, float& c3,
                                         unsigned a0, unsigned a1, unsigned a2, unsigned a3,
                                         unsigned b0, unsigned b1) {
    asm volatile("mma.sync.aligned.m16n8k16.row.col.f32.bf16.bf16.f32 "
                 "{%0,%1,%2,%3},{%4,%5,%6,%7},{%8,%9},{%0,%1,%2,%3};\n"
                 : "+f"(c0), "+f"(c1), "+f"(c2), "+f"(c3)
                 : "r"(a0), "r"(a1), "r"(a2), "r"(a3), "r"(b0), "r"(b1));
}

// ---------------------------------------------------------------- misc zero
__global__ __launch_bounds__(256) void zero_misc_k() {
    int i = blockIdx.x * 256 + threadIdx.x;
    if (i < NN + NPAD) {
        ((float4*)g_eagg)[i] = make_float4(0.f, 0.f, 0.f, 0.f);
    }
    if (i < NN) g_deg[i] = 0;
    if (i < BB * HH) g_pool[i] = 0.f;
    if (i < BB) g_cnt[i] = 0;
}

// ---------------------------------------------------------------- degree + edge-attr agg
__global__ __launch_bounds__(256) void deg_eagg_k(const int* __restrict__ ei,
                                                  const float* __restrict__ ea) {
    int e = blockIdx.x * 256 + threadIdx.x;
    if (e >= EE) return;
    int dst = ei[EE + e];
    atomicAdd(&g_deg[dst], 1);
    atomicAdd(&g_eagg[dst * 4 + 0], ea[e * 3 + 0]);
    atomicAdd(&g_eagg[dst * 4 + 1], ea[e * 3 + 1]);
    atomicAdd(&g_eagg[dst * 4 + 2], ea[e * 3 + 2]);
}

// ---------------------------------------------------------------- one-block scan
__global__ __launch_bounds__(1024) void scan_k() {
    __shared__ int sums[1024];
    int tid = threadIdx.x;
    const int CH = (NN + 1023) / 1024;
    int base = tid * CH;
    int s = 0;
    for (int i = 0; i < CH; i++) {
        int n = base + i;
        if (n < NN) s += g_deg[n];
    }
    sums[tid] = s;
    __syncthreads();
    for (int off = 1; off < 1024; off <<= 1) {
        int v = sums[tid];
        int add = (tid >= off) ? sums[tid - off] : 0;
        __syncthreads();
        sums[tid] = v + add;
        __syncthreads();
    }
    int run = sums[tid] - s;
    for (int i = 0; i < CH; i++) {
        int n = base + i;
        if (n < NN) {
            g_start[n] = run;
            g_cursor[n] = run;
            run += g_deg[n];
        }
    }
    if (tid == 0) g_start[NN] = EE;
}

// ---------------------------------------------------------------- edge reorder (CSR by dst)
__global__ __launch_bounds__(256) void reorder_k(const int* __restrict__ ei) {
    int e = blockIdx.x * 256 + threadIdx.x;
    if (e >= EE) return;
    int dst = ei[EE + e];
    int pos = atomicAdd(&g_cursor[dst], 1);
    g_srcs[pos] = ei[e];
}

// ---------------------------------------------------------------- weight pack (split bf16)
__global__ __launch_bounds__(256) void pack_all_k(const float* __restrict__ mW1,
                                                  const float* __restrict__ mW2,
                                                  const float* __restrict__ oW1,
                                                  const float* __restrict__ oW2) {
    int idx = blockIdx.x * 256 + threadIdx.x;
    if (idx < 49152) {
        int l = idx / 16384, r = idx % 16384;
        int k2 = r / 256, n = r % 256;
        const float* src = mW1 + l * (128 * 256);
        g_W1p[idx] = splitpack2(src[(2 * k2) * 256 + n], src[(2 * k2 + 1) * 256 + n]);
        return;
    }
    int j = idx - 49152;
    if (j < 49152) {
        int l = j / 16384, r = j % 16384;
        int k2 = r / 128, n = r % 128;
        const float* src = mW2 + l * (256 * 128);
        g_W2p[j] = splitpack2(src[(2 * k2) * 128 + n], src[(2 * k2 + 1) * 128 + n]);
        return;
    }
    j -= 49152;
    if (j < 32768) {
        int k2 = j / 128, n = j % 128;
        g_oW1p[j] = splitpack2(oW1[(2 * k2) * 128 + n], oW1[(2 * k2 + 1) * 128 + n]);
        return;
    }
    j -= 32768;
    if (j < 8192) {
        int k2 = j / 128, n = j % 128;
        g_oW2p[j] = splitpack2(oW2[(2 * k2) * 128 + n], oW2[(2 * k2 + 1) * 128 + n]);
    }
}

// ---------------------------------------------------------------- BN fold
__global__ __launch_bounds__(256) void bnprep_k(const float* __restrict__ b1, const float* __restrict__ g1,
                                                const float* __restrict__ bb1, const float* __restrict__ rm1,
                                                const float* __restrict__ rv1,
                                                const float* __restrict__ b2, const float* __restrict__ g2,
                                                const float* __restrict__ bb2, const float* __restrict__ rm2,
                                                const float* __restrict__ rv2) {
    int i = blockIdx.x * 256 + threadIdx.x;
    if (i < LL * 256) {
        float s = g1[i] * rsqrtf(rv1[i] + 1e-5f);
        g_c1a[i] = s;
        g_c1b[i] = (b1[i] - rm1[i]) * s + bb1[i];
    }
    if (i < LL * 128) {
        float s = g2[i] * rsqrtf(rv2[i] + 1e-5f);
        g_c2a[i] = s;
        g_c2b[i] = (b2[i] - rm2[i]) * s + bb2[i];
    }
}

// ---------------------------------------------------------------- input proj
__global__ __launch_bounds__(256) void in_proj_k(const float* __restrict__ x,
                                                 const float* __restrict__ W,
                                                 const float* __restrict__ b) {
    int idx = blockIdx.x * 256 + threadIdx.x;
    int n = idx >> 7, c = idx & 127;
    const float* xr = x + n * 12;
    float acc = b[c];
#pragma unroll
    for (int k = 0; k < 12; k++) acc += xr[k] * W[k * HH + c];
    g_cat[(size_t)n * CATW + c] = acc;
}

// ---------------------------------------------------------------- fused GIN layer
// block = 64 nodes, 256 threads (8 warps)
// smem: zsp uint2[64][66] (33792B) | t1p uint2[64][130] (66560B) = 100352B
__global__ __launch_bounds__(256) void mlp_k(const float* __restrict__ eW,
                                             const float* __restrict__ ebias,
                                             const float* __restrict__ epsp,
                                             const float* __restrict__ lng,
                                             const float* __restrict__ lnb,
                                             int layer) {
    extern __shared__ unsigned char sm_raw[];
    uint2* zsp = (uint2*)sm_raw;                       // [64][66]
    uint2* t1p = (uint2*)(sm_raw + 33792);             // [64][130]
    float* zsf = (float*)sm_raw;                       // alias: [64][132]

    int tid = threadIdx.x;
    int w = tid >> 5, lane = tid & 31;
    int g = lane >> 2, tig = lane & 3;
    int n0 = blockIdx.x * 64;
    float eps1 = 1.f + epsp[layer];

    // ---- stage A: z = (1+eps)h + sum_src h[src] + eagg@W_e + deg*b_e -> zsp
    {
        int c0 = lane * 4;
        float4 ew0 = *(const float4*)&eW[0 * HH + c0];
        float4 ew1 = *(const float4*)&eW[1 * HH + c0];
        float4 ew2 = *(const float4*)&eW[2 * HH + c0];
        float4 eb4 = *(const float4*)&ebias[c0];
        const float* hb = g_cat + layer * HH + c0;
#pragma unroll
        for (int rr = 0; rr < 8; rr++) {
            int rl = w * 8 + rr;
            int n = n0 + rl;
            if (n < NN) {
                float4 h4 = *(const float4*)(hb + (size_t)n * CATW);
                float e0 = g_eagg[n * 4 + 0], e1 = g_eagg[n * 4 + 1], e2 = g_eagg[n * 4 + 2];
                int s0 = g_start[n], s1 = g_start[n + 1];
                float dg = (float)(s1 - s0);
                float ax = eps1 * h4.x + e0 * ew0.x + e1 * ew1.x + e2 * ew2.x + dg * eb4.x;
                float ay = eps1 * h4.y + e0 * ew0.y + e1 * ew1.y + e2 * ew2.y + dg * eb4.y;
                float az = eps1 * h4.z + e0 * ew0.z + e1 * ew1.z + e2 * ew2.z + dg * eb4.z;
                float aw = eps1 * h4.w + e0 * ew0.w + e1 * ew1.w + e2 * ew2.w + dg * eb4.w;
                int e = s0;
                for (; e + 4 <= s1; e += 4) {
                    int sa = g_srcs[e], sb = g_srcs[e + 1], sc = g_srcs[e + 2], sd = g_srcs[e + 3];
                    float4 va = *(const float4*)(hb + (size_t)sa * CATW);
                    float4 vb = *(const float4*)(hb + (size_t)sb * CATW);
                    float4 vc = *(const float4*)(hb + (size_t)sc * CATW);
                    float4 vd = *(const float4*)(hb + (size_t)sd * CATW);
                    ax += (va.x + vb.x) + (vc.x + vd.x);
                    ay += (va.y + vb.y) + (vc.y + vd.y);
                    az += (va.z + vb.z) + (vc.z + vd.z);
                    aw += (va.w + vb.w) + (vc.w + vd.w);
                }
                for (; e < s1; e++) {
                    int src = g_srcs[e];
                    float4 v = *(const float4*)(hb + (size_t)src * CATW);
                    ax += v.x; ay += v.y; az += v.z; aw += v.w;
                }
                uint2 p0 = splitpack2(ax, ay);
                uint2 p1 = splitpack2(az, aw);
                ((uint4*)zsp)[rl * 33 + lane] = make_uint4(p0.x, p0.y, p1.x, p1.y);
            } else {
                ((uint4*)zsp)[rl * 33 + lane] = make_uint4(0u, 0u, 0u, 0u);
            }
        }
    }
    __syncthreads();

    // ---- GEMM1: [64x128] @ [128x256] -> bn1 relu -> t1p
    // warp w owns cols [w*32, w*32+32); loops 4 row-tiles reusing weight frags
    {
        const uint2* Wp = g_W1p + layer * (64 * 256);
        int nb = w * 32;
        float c[4][4][4];
#pragma unroll
        for (int rt = 0; rt < 4; rt++)
#pragma unroll
            for (int t = 0; t < 4; t++) { c[rt][t][0] = c[rt][t][1] = c[rt][t][2] = c[rt][t][3] = 0.f; }

        for (int kb2 = 0; kb2 < 64; kb2 += 8) {
            uint2 q0[4], q1[4];
#pragma unroll
            for (int t = 0; t < 4; t++) {
                int n = nb + t * 8 + g;
                q0[t] = Wp[(kb2 + tig) * 256 + n];
                q1[t] = Wp[(kb2 + 4 + tig) * 256 + n];
            }
#pragma unroll
            for (int rt = 0; rt < 4; rt++) {
                int r = rt * 16;
                uint2 r0 = zsp[(r + g) * 66 + kb2 + tig];
                uint2 r1 = zsp[(r + g + 8) * 66 + kb2 + tig];
                uint2 r2 = zsp[(r + g) * 66 + kb2 + 4 + tig];
                uint2 r3 = zsp[(r + g + 8) * 66 + kb2 + 4 + tig];
#pragma unroll
                for (int t = 0; t < 4; t++) {
                    mma_bf16(c[rt][t][0], c[rt][t][1], c[rt][t][2], c[rt][t][3],
                             r0.x, r1.x, r2.x, r3.x, q0[t].x, q1[t].x);
                    mma_bf16(c[rt][t][0], c[rt][t][1], c[rt][t][2], c[rt][t][3],
                             r0.x, r1.x, r2.x, r3.x, q0[t].y, q1[t].y);
                    mma_bf16(c[rt][t][0], c[rt][t][1], c[rt][t][2], c[rt][t][3],
                             r0.y, r1.y, r2.y, r3.y, q0[t].x, q1[t].x);
                }
            }
        }
        const float* A1 = g_c1a + layer * 256;
        const float* B1 = g_c1b + layer * 256;
#pragma unroll
        for (int rt = 0; rt < 4; rt++) {
#pragma unroll
            for (int t = 0; t < 4; t++) {
                int col = nb + t * 8 + tig * 2;
                float a0 = A1[col], b0 = B1[col], a1 = A1[col + 1], b1 = B1[col + 1];
                float v00 = fmaxf(c[rt][t][0] * a0 + b0, 0.f);
                float v01 = fmaxf(c[rt][t][1] * a1 + b1, 0.f);
                float v10 = fmaxf(c[rt][t][2] * a0 + b0, 0.f);
                float v11 = fmaxf(c[rt][t][3] * a1 + b1, 0.f);
                int c2 = col >> 1;
                t1p[(rt * 16 + g) * 130 + c2] = splitpack2(v00, v01);
                t1p[(rt * 16 + g + 8) * 130 + c2] = splitpack2(v10, v11);
            }
        }
    }
    __syncthreads();

    // ---- GEMM2: [64x256] @ [256x128] -> bn2 relu + residual -> zsf
    // warp w owns cols [w*16, w*16+16)
    {
        const uint2* Wp = g_W2p + layer * (128 * 128);
        int nb = w * 16;
        float c[4][2][4];
#pragma unroll
        for (int rt = 0; rt < 4; rt++)
#pragma unroll
            for (int t = 0; t < 2; t++) { c[rt][t][0] = c[rt][t][1] = c[rt][t][2] = c[rt][t][3] = 0.f; }

        for (int kb2 = 0; kb2 < 128; kb2 += 8) {
            uint2 q0[2], q1[2];
#pragma unroll
            for (int t = 0; t < 2; t++) {
                int n = nb + t * 8 + g;
                q0[t] = Wp[(kb2 + tig) * 128 + n];
                q1[t] = Wp[(kb2 + 4 + tig) * 128 + n];
            }
#pragma unroll
            for (int rt = 0; rt < 4; rt++) {
                int r = rt * 16;
                uint2 r0 = t1p[(r + g) * 130 + kb2 + tig];
                uint2 r1 = t1p[(r + g + 8) * 130 + kb2 + tig];
                uint2 r2 = t1p[(r + g) * 130 + kb2 + 4 + tig];
                uint2 r3 = t1p[(r + g + 8) * 130 + kb2 + 4 + tig];
#pragma unroll
                for (int t = 0; t < 2; t++) {
                    mma_bf16(c[rt][t][0], c[rt][t][1], c[rt][t][2], c[rt][t][3],
                             r0.x, r1.x, r2.x, r3.x, q0[t].x, q1[t].x);
                    mma_bf16(c[rt][t][0], c[rt][t][1], c[rt][t][2], c[rt][t][3],
                             r0.x, r1.x, r2.x, r3.x, q0[t].y, q1[t].y);
                    mma_bf16(c[rt][t][0], c[rt][t][1], c[rt][t][2], c[rt][t][3],
                             r0.y, r1.y, r2.y, r3.y, q0[t].x, q1[t].x);
                }
            }
        }
        const float* A2 = g_c2a + layer * 128;
        const float* B2 = g_c2b + layer * 128;
#pragma unroll
        for (int rt = 0; rt < 4; rt++) {
#pragma unroll
            for (int t = 0; t < 2; t++) {
                int col = nb + t * 8 + tig * 2;
                float a0 = A2[col], b0 = B2[col], a1 = A2[col + 1], b1 = B2[col + 1];
                int r0w = rt * 16 + g, r1w = rt * 16 + g + 8;
                const float* h0 = g_cat + (size_t)(n0 + r0w) * CATW + layer * HH + col;
                const float* h1 = g_cat + (size_t)(n0 + r1w) * CATW + layer * HH + col;
                zsf[r0w * 132 + col]     = fmaxf(c[rt][t][0] * a0 + b0, 0.f) + h0[0];
                zsf[r0w * 132 + col + 1] = fmaxf(c[rt][t][1] * a1 + b1, 0.f) + h0[1];
                zsf[r1w * 132 + col]     = fmaxf(c[rt][t][2] * a0 + b0, 0.f) + h1[0];
                zsf[r1w * 132 + col + 1] = fmaxf(c[rt][t][3] * a1 + b1, 0.f) + h1[1];
            }
        }
    }
    __syncthreads();

    // ---- LayerNorm rows -> g_cat layer+1
    {
#pragma unroll
        for (int rr = 0; rr < 8; rr++) {
            int m = w * 8 + rr;
            float4 v = *(const float4*)&zsf[m * 132 + lane * 4];
            float sum = v.x + v.y + v.z + v.w;
            float sq = v.x * v.x + v.y * v.y + v.z * v.z + v.w * v.w;
#pragma unroll
            for (int o = 16; o; o >>= 1) {
                sum += __shfl_xor_sync(0xffffffffu, sum, o);
                sq += __shfl_xor_sync(0xffffffffu, sq, o);
            }
            float mu = sum * (1.f / 128.f);
            float var = sq * (1.f / 128.f) - mu * mu;
            float inv = rsqrtf(var + 1e-5f);
            int n = n0 + m;
            if (n < NN) {
                int c0 = lane * 4;
                float4 o;
                o.x = (v.x - mu) * inv * lng[c0 + 0] + lnb[c0 + 0];
                o.y = (v.y - mu) * inv * lng[c0 + 1] + lnb[c0 + 1];
                o.z = (v.z - mu) * inv * lng[c0 + 2] + lnb[c0 + 2];
                o.w = (v.w - mu) * inv * lng[c0 + 3] + lnb[c0 + 3];
                *(float4*)&g_cat[(size_t)n * CATW + (layer + 1) * HH + c0] = o;
            }
        }
    }
}

// ---------------------------------------------------------------- graph counts
__global__ __launch_bounds__(256) void count_k(const int* __restrict__ batch) {
    __shared__ int sc[BB];
    int tid = threadIdx.x;
    if (tid < BB) sc[tid] = 0;
    __syncthreads();
    int n = blockIdx.x * 256 + tid;
    if (n < NN) atomicAdd(&sc[batch[n]], 1);
    __syncthreads();
    if (tid < BB) atomicAdd(&g_cnt[tid], sc[tid]);
}

// ---------------------------------------------------------------- output head
// block = 64 nodes; smem: catp uint2[64][258] (132096B) | t1p uint2[64][66] (33792B) = 165888B
__global__ __launch_bounds__(256) void out_k(const float* __restrict__ ob1,
                                             const float* __restrict__ ob2,
                                             const int* __restrict__ batch,
                                             float* __restrict__ out) {
    extern __shared__ unsigned char sm_raw[];
    uint2* catp = (uint2*)sm_raw;                     // [64][258]
    uint2* t1p = (uint2*)(sm_raw + 132096);           // [64][66]

    int tid = threadIdx.x;
    int w = tid >> 5, lane = tid & 31;
    int g = lane >> 2, tig = lane & 3;
    int n0 = blockIdx.x * 64;

    // split-pack the 64x512 cat tile (padded g_cat: unguarded reads OK)
#pragma unroll
    for (int i = 0; i < 32; i++) {
        int idx = tid + i * 256;          // 0..8191 (64 rows x 128 float4)
        int n = idx >> 7, c4 = idx & 127;
        float4 v = *(const float4*)(g_cat + (size_t)(n0 + n) * CATW + c4 * 4);
        uint2 p0 = splitpack2(v.x, v.y);
        uint2 p1 = splitpack2(v.z, v.w);
        ((uint4*)catp)[n * 129 + c4] = make_uint4(p0.x, p0.y, p1.x, p1.y);
    }
    __syncthreads();

    int nb = w * 16;

    // GEMM1: [64x512] @ [512x128] -> relu -> t1p
    {
        float c[4][2][4];
#pragma unroll
        for (int rt = 0; rt < 4; rt++)
#pragma unroll
            for (int t = 0; t < 2; t++) { c[rt][t][0] = c[rt][t][1] = c[rt][t][2] = c[rt][t][3] = 0.f; }

        for (int kb2 = 0; kb2 < 256; kb2 += 8) {
            uint2 q0[2], q1[2];
#pragma unroll
            for (int t = 0; t < 2; t++) {
                int n = nb + t * 8 + g;
                q0[t] = g_oW1p[(kb2 + tig) * 128 + n];
                q1[t] = g_oW1p[(kb2 + 4 + tig) * 128 + n];
            }
#pragma unroll
            for (int rt = 0; rt < 4; rt++) {
                int r = rt * 16;
                uint2 r0 = catp[(r + g) * 258 + kb2 + tig];
                uint2 r1 = catp[(r + g + 8) * 258 + kb2 + tig];
                uint2 r2 = catp[(r + g) * 258 + kb2 + 4 + tig];
                uint2 r3 = catp[(r + g + 8) * 258 + kb2 + 4 + tig];
#pragma unroll
                for (int t = 0; t < 2; t++) {
                    mma_bf16(c[rt][t][0], c[rt][t][1], c[rt][t][2], c[rt][t][3],
                             r0.x, r1.x, r2.x, r3.x, q0[t].x, q1[t].x);
                    mma_bf16(c[rt][t][0], c[rt][t][1], c[rt][t][2], c[rt][t][3],
                             r0.x, r1.x, r2.x, r3.x, q0[t].y, q1[t].y);
                    mma_bf16(c[rt][t][0], c[rt][t][1], c[rt][t][2], c[rt][t][3],
                             r0.y, r1.y, r2.y, r3.y, q0[t].x, q1[t].x);
                }
            }
        }
#pragma unroll
        for (int rt = 0; rt < 4; rt++) {
#pragma unroll
            for (int t = 0; t < 2; t++) {
                int col = nb + t * 8 + tig * 2;
                float b0 = ob1[col], b1 = ob1[col + 1];
                float v00 = fmaxf(c[rt][t][0] + b0, 0.f);
                float v01 = fmaxf(c[rt][t][1] + b1, 0.f);
                float v10 = fmaxf(c[rt][t][2] + b0, 0.f);
                float v11 = fmaxf(c[rt][t][3] + b1, 0.f);
                int c2 = col >> 1;
                t1p[(rt * 16 + g) * 66 + c2] = splitpack2(v00, v01);
                t1p[(rt * 16 + g + 8) * 66 + c2] = splitpack2(v10, v11);
            }
        }
    }
    __syncthreads();

    // GEMM2: [64x128] @ [128x128] -> out + pool
    {
        float c[4][2][4];
#pragma unroll
        for (int rt = 0; rt < 4; rt++)
#pragma unroll
            for (int t = 0; t < 2; t++) { c[rt][t][0] = c[rt][t][1] = c[rt][t][2] = c[rt][t][3] = 0.f; }

        for (int kb2 = 0; kb2 < 64; kb2 += 8) {
            uint2 q0[2], q1[2];
#pragma unroll
            for (int t = 0; t < 2; t++) {
                int n = nb + t * 8 + g;
                q0[t] = g_oW2p[(kb2 + tig) * 128 + n];
                q1[t] = g_oW2p[(kb2 + 4 + tig) * 128 + n];
            }
#pragma unroll
            for (int rt = 0; rt < 4; rt++) {
                int r = rt * 16;
                uint2 r0 = t1p[(r + g) * 66 + kb2 + tig];
                uint2 r1 = t1p[(r + g + 8) * 66 + kb2 + tig];
                uint2 r2 = t1p[(r + g) * 66 + kb2 + 4 + tig];
                uint2 r3 = t1p[(r + g + 8) * 66 + kb2 + 4 + tig];
#pragma unroll
                for (int t = 0; t < 2; t++) {
                    mma_bf16(c[rt][t][0], c[rt][t][1], c[rt][t][2], c[rt][t][3],
                             r0.x, r1.x, r2.x, r3.x, q0[t].x, q1[t].x);
                    mma_bf16(c[rt][t][0], c[rt][t][1], c[rt][t][2], c[rt][t][3],
                             r0.x, r1.x, r2.x, r3.x, q0[t].y, q1[t].y);
                    mma_bf16(c[rt][t][0], c[rt][t][1], c[rt][t][2], c[rt][t][3],
                             r0.y, r1.y, r2.y, r3.y, q0[t].x, q1[t].x);
                }
            }
        }
#pragma unroll
        for (int rt = 0; rt < 4; rt++) {
            int nA = n0 + rt * 16 + g;
            int nB = nA + 8;
            int bA = (nA < NN) ? batch[nA] : 0;
            int bB = (nB < NN) ? batch[nB] : 0;
#pragma unroll
            for (int t = 0; t < 2; t++) {
                int col = nb + t * 8 + tig * 2;
                float b0 = ob2[col], b1 = ob2[col + 1];
                float v00 = c[rt][t][0] + b0, v01 = c[rt][t][1] + b1;
                float v10 = c[rt][t][2] + b0, v11 = c[rt][t][3] + b1;
                if (nA < NN) {
                    out[(size_t)nA * HH + col] = v00;
                    out[(size_t)nA * HH + col + 1] = v01;
                    atomicAdd(&g_pool[bA * HH + col], v00);
                    atomicAdd(&g_pool[bA * HH + col + 1], v01);
                }
                if (nB < NN) {
                    out[(size_t)nB * HH + col] = v10;
                    out[(size_t)nB * HH + col + 1] = v11;
                    atomicAdd(&g_pool[bB * HH + col], v10);
                    atomicAdd(&g_pool[bB * HH + col + 1], v11);
                }
            }
        }
    }
}

// ---------------------------------------------------------------- pool divide
__global__ __launch_bounds__(256) void pooldiv_k(float* __restrict__ out) {
    int i = blockIdx.x * 256 + threadIdx.x;
    if (i < BB * HH) {
        int b = i >> 7;
        float c = (float)g_cnt[b];
        out[(size_t)NN * HH + i] = g_pool[i] / fmaxf(c, 1.f);
    }
}

// ---------------------------------------------------------------- launch
extern "C" void kernel_launch(void* const* d_in, const int* in_sizes, int n_in,
                              void* d_out, int out_size) {
    const float* x      = (const float*)d_in[0];
    const int*   ei     = (const int*)d_in[1];
    const float* ea     = (const float*)d_in[2];
    const int*   batch  = (const int*)d_in[3];
    const float* in_W   = (const float*)d_in[4];
    const float* in_b   = (const float*)d_in[5];
    const float* edge_W = (const float*)d_in[6];
    const float* edge_b = (const float*)d_in[7];
    const float* mlp_W1 = (const float*)d_in[8];
    const float* mlp_b1 = (const float*)d_in[9];
    const float* bn1_g  = (const float*)d_in[10];
    const float* bn1_b  = (const float*)d_in[11];
    const float* bn1_rm = (const float*)d_in[12];
    const float* bn1_rv = (const float*)d_in[13];
    const float* mlp_W2 = (const float*)d_in[14];
    const float* mlp_b2 = (const float*)d_in[15];
    const float* bn2_g  = (const float*)d_in[16];
    const float* bn2_b  = (const float*)d_in[17];
    const float* bn2_rm = (const float*)d_in[18];
    const float* bn2_rv = (const float*)d_in[19];
    const float* epsp   = (const float*)d_in[20];
    const float* ln_g   = (const float*)d_in[21];
    const float* ln_b   = (const float*)d_in[22];
    const float* out_W1 = (const float*)d_in[23];
    const float* out_b1 = (const float*)d_in[24];
    const float* out_W2 = (const float*)d_in[25];
    const float* out_b2 = (const float*)d_in[26];
    float* out = (float*)d_out;

    cudaFuncSetAttribute(mlp_k, cudaFuncAttributeMaxDynamicSharedMemorySize, 100352);
    cudaFuncSetAttribute(out_k, cudaFuncAttributeMaxDynamicSharedMemorySize, 165888);

    // preprocessing
    zero_misc_k<<<(NN + NPAD + 255) / 256, 256>>>();
    deg_eagg_k<<<(EE + 255) / 256, 256>>>(ei, ea);
    scan_k<<<1, 1024>>>();
    reorder_k<<<(EE + 255) / 256, 256>>>(ei);
    pack_all_k<<<(139264 + 255) / 256, 256>>>(mlp_W1, mlp_W2, out_W1, out_W2);
    bnprep_k<<<3, 256>>>(mlp_b1, bn1_g, bn1_b, bn1_rm, bn1_rv,
                         mlp_b2, bn2_g, bn2_b, bn2_rm, bn2_rv);

    in_proj_k<<<NN * HH / 256, 256>>>(x, in_W, in_b);
    count_k<<<(NN + 255) / 256, 256>>>(batch);

    const int NB = (NN + 63) / 64;   // 1563
    for (int l = 0; l < LL; l++) {
        mlp_k<<<NB, 256, 100352>>>(edge_W + l * 3 * HH, edge_b + l * HH,
                                   epsp, ln_g + l * HH, ln_b + l * HH, l);
    }

    out_k<<<NB, 256, 165888>>>(out_b1, out_b2, batch, out);
    pooldiv_k<<<8, 256>>>(out);
}

// round 12
// speedup vs baseline: 2.2031x; 1.4689x over previous
#include <cuda_runtime.h>
#include <cuda_bf16.h>

#define NN 100000
#define EE 600000
#define HH 128
#define LL 3
#define BB 16
#define CATW 512   // (LL+1)*HH
#define NPAD 64    // tail padding rows

// ---- scratch (device globals: no allocation allowed) ----
__device__ float g_cat[(size_t)(NN + NPAD) * CATW];
__device__ int   g_deg[NN];
__device__ int   g_start[NN + 1];
__device__ int   g_cursor[NN];
__device__ int   g_srcs[EE];
__device__ float g_eagg[(NN + NPAD) * 4];
__device__ float g_pool[BB * HH];
__device__ int   g_cnt[BB];
// split-bf16 packed weights: uint2 {hi_pair(k,k+1), lo_pair}
__device__ uint2 g_W1p[LL * 64 * 256];
__device__ uint2 g_W2p[LL * 128 * 128];
__device__ uint2 g_oW1p[256 * 128];
__device__ uint2 g_oW2p[64 * 128];
// folded BN: v = acc*a + b
__device__ float g_c1a[LL * 256], g_c1b[LL * 256];
__device__ float g_c2a[LL * 128], g_c2b[LL * 128];

// ---------------------------------------------------------------- helpers
__device__ __forceinline__ uint2 splitpack2(float x0, float x1) {
    __nv_bfloat16 h0 = __float2bfloat16(x0);
    __nv_bfloat16 h1 = __float2bfloat16(x1);
    float r0 = x0 - __bfloat162float(h0);
    float r1 = x1 - __bfloat162float(h1);
    __nv_bfloat16 l0 = __float2bfloat16(r0);
    __nv_bfloat16 l1 = __float2bfloat16(r1);
    unsigned hu = (unsigned)__bfloat16_as_ushort(h0) | ((unsigned)__bfloat16_as_ushort(h1) << 16);
    unsigned lu = (unsigned)__bfloat16_as_ushort(l0) | ((unsigned)__bfloat16_as_ushort(l1) << 16);
    return make_uint2(hu, lu);
}

__device__ __forceinline__ void mma_bf16(float& c0, float& c1, float& c2, float& c3,
                                         unsigned a0, unsigned a1, unsigned a2, unsigned a3,
                                         unsigned b0, unsigned b1) {
    asm volatile("mma.sync.aligned.m16n8k16.row.col.f32.bf16.bf16.f32 "
                 "{%0,%1,%2,%3},{%4,%5,%6,%7},{%8,%9},{%0,%1,%2,%3};\n"
                 : "+f"(c0), "+f"(c1), "+f"(c2), "+f"(c3)
                 : "r"(a0), "r"(a1), "r"(a2), "r"(a3), "r"(b0), "r"(b1));
}

// ---------------------------------------------------------------- misc zero
__global__ __launch_bounds__(256) void zero_misc_k() {
    int i = blockIdx.x * 256 + threadIdx.x;
    if (i < NN + NPAD) ((float4*)g_eagg)[i] = make_float4(0.f, 0.f, 0.f, 0.f);
    if (i < NN) g_deg[i] = 0;
    if (i < BB * HH) g_pool[i] = 0.f;
    if (i < BB) g_cnt[i] = 0;
}

// ---------------------------------------------------------------- degree + edge-attr agg
__global__ __launch_bounds__(256) void deg_eagg_k(const int* __restrict__ ei,
                                                  const float* __restrict__ ea) {
    int e = blockIdx.x * 256 + threadIdx.x;
    if (e >= EE) return;
    int dst = ei[EE + e];
    atomicAdd(&g_deg[dst], 1);
    atomicAdd(&g_eagg[dst * 4 + 0], ea[e * 3 + 0]);
    atomicAdd(&g_eagg[dst * 4 + 1], ea[e * 3 + 1]);
    atomicAdd(&g_eagg[dst * 4 + 2], ea[e * 3 + 2]);
}

// ---------------------------------------------------------------- one-block scan
__global__ __launch_bounds__(1024) void scan_k() {
    __shared__ int sums[1024];
    int tid = threadIdx.x;
    const int CH = (NN + 1023) / 1024;
    int base = tid * CH;
    int s = 0;
    for (int i = 0; i < CH; i++) {
        int n = base + i;
        if (n < NN) s += g_deg[n];
    }
    sums[tid] = s;
    __syncthreads();
    for (int off = 1; off < 1024; off <<= 1) {
        int v = sums[tid];
        int add = (tid >= off) ? sums[tid - off] : 0;
        __syncthreads();
        sums[tid] = v + add;
        __syncthreads();
    }
    int run = sums[tid] - s;
    for (int i = 0; i < CH; i++) {
        int n = base + i;
        if (n < NN) {
            g_start[n] = run;
            g_cursor[n] = run;
            run += g_deg[n];
        }
    }
    if (tid == 0) g_start[NN] = EE;
}

// ---------------------------------------------------------------- edge reorder (CSR by dst)
__global__ __launch_bounds__(256) void reorder_k(const int* __restrict__ ei) {
    int e = blockIdx.x * 256 + threadIdx.x;
    if (e >= EE) return;
    int dst = ei[EE + e];
    int pos = atomicAdd(&g_cursor[dst], 1);
    g_srcs[pos] = ei[e];
}

// ---------------------------------------------------------------- fused preprocessing
// blocks [0,50000): in_proj ; [50000,50544): weight pack ; [50544,50935): count ;
// [50935,50938): bn fold.  All mutually independent.
#define MP_INPROJ 50000
#define MP_PACK   (MP_INPROJ + 544)
#define MP_COUNT  (MP_PACK + 391)
#define MP_TOTAL  (MP_COUNT + 3)

__global__ __launch_bounds__(256) void mega_prep_k(
    const float* __restrict__ x, const float* __restrict__ in_W, const float* __restrict__ in_b,
    const float* __restrict__ mW1, const float* __restrict__ mW2,
    const float* __restrict__ oW1, const float* __restrict__ oW2,
    const int* __restrict__ batch,
    const float* __restrict__ b1, const float* __restrict__ g1, const float* __restrict__ bb1,
    const float* __restrict__ rm1, const float* __restrict__ rv1,
    const float* __restrict__ b2, const float* __restrict__ g2, const float* __restrict__ bb2,
    const float* __restrict__ rm2, const float* __restrict__ rv2) {
    int blk = blockIdx.x;
    int tid = threadIdx.x;

    if (blk < MP_INPROJ) {
        // ---- input projection: h0 = x @ in_W + in_b
        int idx = blk * 256 + tid;
        int n = idx >> 7, c = idx & 127;
        const float* xr = x + n * 12;
        float acc = in_b[c];
#pragma unroll
        for (int k = 0; k < 12; k++) acc += xr[k] * in_W[k * HH + c];
        g_cat[(size_t)n * CATW + c] = acc;
        return;
    }
    if (blk < MP_PACK) {
        // ---- split-bf16 weight packing (139264 elements)
        int idx = (blk - MP_INPROJ) * 256 + tid;
        if (idx < 49152) {
            int l = idx / 16384, r = idx % 16384;
            int k2 = r / 256, n = r % 256;
            const float* src = mW1 + l * (128 * 256);
            g_W1p[idx] = splitpack2(src[(2 * k2) * 256 + n], src[(2 * k2 + 1) * 256 + n]);
            return;
        }
        int j = idx - 49152;
        if (j < 49152) {
            int l = j / 16384, r = j % 16384;
            int k2 = r / 128, n = r % 128;
            const float* src = mW2 + l * (256 * 128);
            g_W2p[j] = splitpack2(src[(2 * k2) * 128 + n], src[(2 * k2 + 1) * 128 + n]);
            return;
        }
        j -= 49152;
        if (j < 32768) {
            int k2 = j / 128, n = j % 128;
            g_oW1p[j] = splitpack2(oW1[(2 * k2) * 128 + n], oW1[(2 * k2 + 1) * 128 + n]);
            return;
        }
        j -= 32768;
        if (j < 8192) {
            int k2 = j / 128, n = j % 128;
            g_oW2p[j] = splitpack2(oW2[(2 * k2) * 128 + n], oW2[(2 * k2 + 1) * 128 + n]);
        }
        return;
    }
    if (blk < MP_COUNT) {
        // ---- graph node counts
        __shared__ int sc[BB];
        if (tid < BB) sc[tid] = 0;
        __syncthreads();
        int n = (blk - MP_PACK) * 256 + tid;
        if (n < NN) atomicAdd(&sc[batch[n]], 1);
        __syncthreads();
        if (tid < BB) atomicAdd(&g_cnt[tid], sc[tid]);
        return;
    }
    {
        // ---- BN fold
        int i = (blk - MP_COUNT) * 256 + tid;
        if (i < LL * 256) {
            float s = g1[i] * rsqrtf(rv1[i] + 1e-5f);
            g_c1a[i] = s;
            g_c1b[i] = (b1[i] - rm1[i]) * s + bb1[i];
        }
        if (i < LL * 128) {
            float s = g2[i] * rsqrtf(rv2[i] + 1e-5f);
            g_c2a[i] = s;
            g_c2b[i] = (b2[i] - rm2[i]) * s + bb2[i];
        }
    }
}

// ---------------------------------------------------------------- fused GIN layer
// block = 64 nodes, 256 threads (8 warps)
// smem: zsp uint2[64][66] (33792B) | t1p uint2[64][130] (66560B) = 100352B
__global__ __launch_bounds__(256) void mlp_k(const float* __restrict__ eW,
                                             const float* __restrict__ ebias,
                                             const float* __restrict__ epsp,
                                             const float* __restrict__ lng,
                                             const float* __restrict__ lnb,
                                             int layer) {
    extern __shared__ unsigned char sm_raw[];
    uint2* zsp = (uint2*)sm_raw;                       // [64][66]
    uint2* t1p = (uint2*)(sm_raw + 33792);             // [64][130]
    float* zsf = (float*)sm_raw;                       // alias: [64][132]

    int tid = threadIdx.x;
    int w = tid >> 5, lane = tid & 31;
    int g = lane >> 2, tig = lane & 3;
    int n0 = blockIdx.x * 64;
    float eps1 = 1.f + epsp[layer];

    // ---- stage A: z = (1+eps)h + sum_src h[src] + eagg@W_e + deg*b_e -> zsp
    {
        int c0 = lane * 4;
        float4 ew0 = *(const float4*)&eW[0 * HH + c0];
        float4 ew1 = *(const float4*)&eW[1 * HH + c0];
        float4 ew2 = *(const float4*)&eW[2 * HH + c0];
        float4 eb4 = *(const float4*)&ebias[c0];
        const float* hb = g_cat + layer * HH + c0;
#pragma unroll
        for (int rr = 0; rr < 8; rr++) {
            int rl = w * 8 + rr;
            int n = n0 + rl;
            if (n < NN) {
                float4 h4 = *(const float4*)(hb + (size_t)n * CATW);
                float e0 = g_eagg[n * 4 + 0], e1 = g_eagg[n * 4 + 1], e2 = g_eagg[n * 4 + 2];
                int s0 = g_start[n], s1 = g_start[n + 1];
                float dg = (float)(s1 - s0);
                float ax = eps1 * h4.x + e0 * ew0.x + e1 * ew1.x + e2 * ew2.x + dg * eb4.x;
                float ay = eps1 * h4.y + e0 * ew0.y + e1 * ew1.y + e2 * ew2.y + dg * eb4.y;
                float az = eps1 * h4.z + e0 * ew0.z + e1 * ew1.z + e2 * ew2.z + dg * eb4.z;
                float aw = eps1 * h4.w + e0 * ew0.w + e1 * ew1.w + e2 * ew2.w + dg * eb4.w;
                int e = s0;
                for (; e + 4 <= s1; e += 4) {
                    int sa = g_srcs[e], sb = g_srcs[e + 1], sc = g_srcs[e + 2], sd = g_srcs[e + 3];
                    float4 va = *(const float4*)(hb + (size_t)sa * CATW);
                    float4 vb = *(const float4*)(hb + (size_t)sb * CATW);
                    float4 vc = *(const float4*)(hb + (size_t)sc * CATW);
                    float4 vd = *(const float4*)(hb + (size_t)sd * CATW);
                    ax += (va.x + vb.x) + (vc.x + vd.x);
                    ay += (va.y + vb.y) + (vc.y + vd.y);
                    az += (va.z + vb.z) + (vc.z + vd.z);
                    aw += (va.w + vb.w) + (vc.w + vd.w);
                }
                for (; e < s1; e++) {
                    int src = g_srcs[e];
                    float4 v = *(const float4*)(hb + (size_t)src * CATW);
                    ax += v.x; ay += v.y; az += v.z; aw += v.w;
                }
                uint2 p0 = splitpack2(ax, ay);
                uint2 p1 = splitpack2(az, aw);
                ((uint4*)zsp)[rl * 33 + lane] = make_uint4(p0.x, p0.y, p1.x, p1.y);
            } else {
                ((uint4*)zsp)[rl * 33 + lane] = make_uint4(0u, 0u, 0u, 0u);
            }
        }
    }
    __syncthreads();

    // ---- GEMM1: [64x128] @ [128x256] -> bn1 relu -> t1p
    {
        const uint2* Wp = g_W1p + layer * (64 * 256);
        int nb = w * 32;
        float c[4][4][4];
#pragma unroll
        for (int rt = 0; rt < 4; rt++)
#pragma unroll
            for (int t = 0; t < 4; t++) { c[rt][t][0] = c[rt][t][1] = c[rt][t][2] = c[rt][t][3] = 0.f; }

        for (int kb2 = 0; kb2 < 64; kb2 += 8) {
            uint2 q0[4], q1[4];
#pragma unroll
            for (int t = 0; t < 4; t++) {
                int n = nb + t * 8 + g;
                q0[t] = Wp[(kb2 + tig) * 256 + n];
                q1[t] = Wp[(kb2 + 4 + tig) * 256 + n];
            }
#pragma unroll
            for (int rt = 0; rt < 4; rt++) {
                int r = rt * 16;
                uint2 r0 = zsp[(r + g) * 66 + kb2 + tig];
                uint2 r1 = zsp[(r + g + 8) * 66 + kb2 + tig];
                uint2 r2 = zsp[(r + g) * 66 + kb2 + 4 + tig];
                uint2 r3 = zsp[(r + g + 8) * 66 + kb2 + 4 + tig];
#pragma unroll
                for (int t = 0; t < 4; t++) {
                    mma_bf16(c[rt][t][0], c[rt][t][1], c[rt][t][2], c[rt][t][3],
                             r0.x, r1.x, r2.x, r3.x, q0[t].x, q1[t].x);
                    mma_bf16(c[rt][t][0], c[rt][t][1], c[rt][t][2], c[rt][t][3],
                             r0.x, r1.x, r2.x, r3.x, q0[t].y, q1[t].y);
                    mma_bf16(c[rt][t][0], c[rt][t][1], c[rt][t][2], c[rt][t][3],
                             r0.y, r1.y, r2.y, r3.y, q0[t].x, q1[t].x);
                }
            }
        }
        const float* A1 = g_c1a + layer * 256;
        const float* B1 = g_c1b + layer * 256;
#pragma unroll
        for (int rt = 0; rt < 4; rt++) {
#pragma unroll
            for (int t = 0; t < 4; t++) {
                int col = nb + t * 8 + tig * 2;
                float a0 = A1[col], b0 = B1[col], a1 = A1[col + 1], b1 = B1[col + 1];
                float v00 = fmaxf(c[rt][t][0] * a0 + b0, 0.f);
                float v01 = fmaxf(c[rt][t][1] * a1 + b1, 0.f);
                float v10 = fmaxf(c[rt][t][2] * a0 + b0, 0.f);
                float v11 = fmaxf(c[rt][t][3] * a1 + b1, 0.f);
                int c2 = col >> 1;
                t1p[(rt * 16 + g) * 130 + c2] = splitpack2(v00, v01);
                t1p[(rt * 16 + g + 8) * 130 + c2] = splitpack2(v10, v11);
            }
        }
    }
    __syncthreads();

    // ---- GEMM2: [64x256] @ [256x128] -> bn2 relu + residual -> zsf
    {
        const uint2* Wp = g_W2p + layer * (128 * 128);
        int nb = w * 16;
        float c[4][2][4];
#pragma unroll
        for (int rt = 0; rt < 4; rt++)
#pragma unroll
            for (int t = 0; t < 2; t++) { c[rt][t][0] = c[rt][t][1] = c[rt][t][2] = c[rt][t][3] = 0.f; }

        for (int kb2 = 0; kb2 < 128; kb2 += 8) {
            uint2 q0[2], q1[2];
#pragma unroll
            for (int t = 0; t < 2; t++) {
                int n = nb + t * 8 + g;
                q0[t] = Wp[(kb2 + tig) * 128 + n];
                q1[t] = Wp[(kb2 + 4 + tig) * 128 + n];
            }
#pragma unroll
            for (int rt = 0; rt < 4; rt++) {
                int r = rt * 16;
                uint2 r0 = t1p[(r + g) * 130 + kb2 + tig];
                uint2 r1 = t1p[(r + g + 8) * 130 + kb2 + tig];
                uint2 r2 = t1p[(r + g) * 130 + kb2 + 4 + tig];
                uint2 r3 = t1p[(r + g + 8) * 130 + kb2 + 4 + tig];
#pragma unroll
                for (int t = 0; t < 2; t++) {
                    mma_bf16(c[rt][t][0], c[rt][t][1], c[rt][t][2], c[rt][t][3],
                             r0.x, r1.x, r2.x, r3.x, q0[t].x, q1[t].x);
                    mma_bf16(c[rt][t][0], c[rt][t][1], c[rt][t][2], c[rt][t][3],
                             r0.x, r1.x, r2.x, r3.x, q0[t].y, q1[t].y);
                    mma_bf16(c[rt][t][0], c[rt][t][1], c[rt][t][2], c[rt][t][3],
                             r0.y, r1.y, r2.y, r3.y, q0[t].x, q1[t].x);
                }
            }
        }
        const float* A2 = g_c2a + layer * 128;
        const float* B2 = g_c2b + layer * 128;
#pragma unroll
        for (int rt = 0; rt < 4; rt++) {
#pragma unroll
            for (int t = 0; t < 2; t++) {
                int col = nb + t * 8 + tig * 2;
                float a0 = A2[col], b0 = B2[col], a1 = A2[col + 1], b1 = B2[col + 1];
                int r0w = rt * 16 + g, r1w = rt * 16 + g + 8;
                const float* h0 = g_cat + (size_t)(n0 + r0w) * CATW + layer * HH + col;
                const float* h1 = g_cat + (size_t)(n0 + r1w) * CATW + layer * HH + col;
                zsf[r0w * 132 + col]     = fmaxf(c[rt][t][0] * a0 + b0, 0.f) + h0[0];
                zsf[r0w * 132 + col + 1] = fmaxf(c[rt][t][1] * a1 + b1, 0.f) + h0[1];
                zsf[r1w * 132 + col]     = fmaxf(c[rt][t][2] * a0 + b0, 0.f) + h1[0];
                zsf[r1w * 132 + col + 1] = fmaxf(c[rt][t][3] * a1 + b1, 0.f) + h1[1];
            }
        }
    }
    __syncthreads();

    // ---- LayerNorm rows -> g_cat layer+1
    {
#pragma unroll
        for (int rr = 0; rr < 8; rr++) {
            int m = w * 8 + rr;
            float4 v = *(const float4*)&zsf[m * 132 + lane * 4];
            float sum = v.x + v.y + v.z + v.w;
            float sq = v.x * v.x + v.y * v.y + v.z * v.z + v.w * v.w;
#pragma unroll
            for (int o = 16; o; o >>= 1) {
                sum += __shfl_xor_sync(0xffffffffu, sum, o);
                sq += __shfl_xor_sync(0xffffffffu, sq, o);
            }
            float mu = sum * (1.f / 128.f);
            float var = sq * (1.f / 128.f) - mu * mu;
            float inv = rsqrtf(var + 1e-5f);
            int n = n0 + m;
            if (n < NN) {
                int c0 = lane * 4;
                float4 o;
                o.x = (v.x - mu) * inv * lng[c0 + 0] + lnb[c0 + 0];
                o.y = (v.y - mu) * inv * lng[c0 + 1] + lnb[c0 + 1];
                o.z = (v.z - mu) * inv * lng[c0 + 2] + lnb[c0 + 2];
                o.w = (v.w - mu) * inv * lng[c0 + 3] + lnb[c0 + 3];
                *(float4*)&g_cat[(size_t)n * CATW + (layer + 1) * HH + c0] = o;
            }
        }
    }
}

// ---------------------------------------------------------------- output head
// block = 64 nodes; smem: catp uint2[64][258] (132096B) | t1p uint2[64][66] (33792B) = 165888B
// After GEMM2: region 0 reused as fbuf float[64][128] (32KB) + bat int[64].
__global__ __launch_bounds__(256) void out_k(const float* __restrict__ ob1,
                                             const float* __restrict__ ob2,
                                             const int* __restrict__ batch,
                                             float* __restrict__ out) {
    extern __shared__ unsigned char sm_raw[];
    uint2* catp = (uint2*)sm_raw;
    uint2* t1p = (uint2*)(sm_raw + 132096);

    int tid = threadIdx.x;
    int w = tid >> 5, lane = tid & 31;
    int g = lane >> 2, tig = lane & 3;
    int n0 = blockIdx.x * 64;

#pragma unroll
    for (int i = 0; i < 32; i++) {
        int idx = tid + i * 256;
        int n = idx >> 7, c4 = idx & 127;
        float4 v = *(const float4*)(g_cat + (size_t)(n0 + n) * CATW + c4 * 4);
        uint2 p0 = splitpack2(v.x, v.y);
        uint2 p1 = splitpack2(v.z, v.w);
        ((uint4*)catp)[n * 129 + c4] = make_uint4(p0.x, p0.y, p1.x, p1.y);
    }
    __syncthreads();

    int nb = w * 16;

    // GEMM1: [64x512] @ [512x128] -> relu -> t1p
    {
        float c[4][2][4];
#pragma unroll
        for (int rt = 0; rt < 4; rt++)
#pragma unroll
            for (int t = 0; t < 2; t++) { c[rt][t][0] = c[rt][t][1] = c[rt][t][2] = c[rt][t][3] = 0.f; }

        for (int kb2 = 0; kb2 < 256; kb2 += 8) {
            uint2 q0[2], q1[2];
#pragma unroll
            for (int t = 0; t < 2; t++) {
                int n = nb + t * 8 + g;
                q0[t] = g_oW1p[(kb2 + tig) * 128 + n];
                q1[t] = g_oW1p[(kb2 + 4 + tig) * 128 + n];
            }
#pragma unroll
            for (int rt = 0; rt < 4; rt++) {
                int r = rt * 16;
                uint2 r0 = catp[(r + g) * 258 + kb2 + tig];
                uint2 r1 = catp[(r + g + 8) * 258 + kb2 + tig];
                uint2 r2 = catp[(r + g) * 258 + kb2 + 4 + tig];
                uint2 r3 = catp[(r + g + 8) * 258 + kb2 + 4 + tig];
#pragma unroll
                for (int t = 0; t < 2; t++) {
                    mma_bf16(c[rt][t][0], c[rt][t][1], c[rt][t][2], c[rt][t][3],
                             r0.x, r1.x, r2.x, r3.x, q0[t].x, q1[t].x);
                    mma_bf16(c[rt][t][0], c[rt][t][1], c[rt][t][2], c[rt][t][3],
                             r0.x, r1.x, r2.x, r3.x, q0[t].y, q1[t].y);
                    mma_bf16(c[rt][t][0], c[rt][t][1], c[rt][t][2], c[rt][t][3],
                             r0.y, r1.y, r2.y, r3.y, q0[t].x, q1[t].x);
                }
            }
        }
#pragma unroll
        for (int rt = 0; rt < 4; rt++) {
#pragma unroll
            for (int t = 0; t < 2; t++) {
                int col = nb + t * 8 + tig * 2;
                float b0 = ob1[col], b1 = ob1[col + 1];
                float v00 = fmaxf(c[rt][t][0] + b0, 0.f);
                float v01 = fmaxf(c[rt][t][1] + b1, 0.f);
                float v10 = fmaxf(c[rt][t][2] + b0, 0.f);
                float v11 = fmaxf(c[rt][t][3] + b1, 0.f);
                int c2 = col >> 1;
                t1p[(rt * 16 + g) * 66 + c2] = splitpack2(v00, v01);
                t1p[(rt * 16 + g + 8) * 66 + c2] = splitpack2(v10, v11);
            }
        }
    }
    __syncthreads();

    // GEMM2: [64x128] @ [128x128]
    float c[4][2][4];
    {
#pragma unroll
        for (int rt = 0; rt < 4; rt++)
#pragma unroll
            for (int t = 0; t < 2; t++) { c[rt][t][0] = c[rt][t][1] = c[rt][t][2] = c[rt][t][3] = 0.f; }

        for (int kb2 = 0; kb2 < 64; kb2 += 8) {
            uint2 q0[2], q1[2];
#pragma unroll
            for (int t = 0; t < 2; t++) {
                int n = nb + t * 8 + g;
                q0[t] = g_oW2p[(kb2 + tig) * 128 + n];
                q1[t] = g_oW2p[(kb2 + 4 + tig) * 128 + n];
            }
#pragma unroll
            for (int rt = 0; rt < 4; rt++) {
                int r = rt * 16;
                uint2 r0 = t1p[(r + g) * 66 + kb2 + tig];
                uint2 r1 = t1p[(r + g + 8) * 66 + kb2 + tig];
                uint2 r2 = t1p[(r + g) * 66 + kb2 + 4 + tig];
                uint2 r3 = t1p[(r + g + 8) * 66 + kb2 + 4 + tig];
#pragma unroll
                for (int t = 0; t < 2; t++) {
                    mma_bf16(c[rt][t][0], c[rt][t][1], c[rt][t][2], c[rt][t][3],
                             r0.x, r1.x, r2.x, r3.x, q0[t].x, q1[t].x);
                    mma_bf16(c[rt][t][0], c[rt][t][1], c[rt][t][2], c[rt][t][3],
                             r0.x, r1.x, r2.x, r3.x, q0[t].y, q1[t].y);
                    mma_bf16(c[rt][t][0], c[rt][t][1], c[rt][t][2], c[rt][t][3],
                             r0.y, r1.y, r2.y, r3.y, q0[t].x, q1[t].x);
                }
            }
        }
    }
    __syncthreads();   // all GEMM reads of catp/t1p done -> safe to reuse region 0

    // epilogue: write out + stage node_emb into smem fbuf, then batched pool reduce
    {
        float* fbuf = (float*)sm_raw;             // [64][128]
        int* bat = (int*)(sm_raw + 32768);        // [64]
#pragma unroll
        for (int rt = 0; rt < 4; rt++) {
            int rA = rt * 16 + g, rB = rA + 8;
            int nA = n0 + rA, nB = n0 + rB;
#pragma unroll
            for (int t = 0; t < 2; t++) {
                int col = nb + t * 8 + tig * 2;
                float b0 = ob2[col], b1 = ob2[col + 1];
                float v00 = c[rt][t][0] + b0, v01 = c[rt][t][1] + b1;
                float v10 = c[rt][t][2] + b0, v11 = c[rt][t][3] + b1;
                fbuf[rA * 128 + col] = v00;
                fbuf[rA * 128 + col + 1] = v01;
                fbuf[rB * 128 + col] = v10;
                fbuf[rB * 128 + col + 1] = v11;
                if (nA < NN) {
                    out[(size_t)nA * HH + col] = v00;
                    out[(size_t)nA * HH + col + 1] = v01;
                }
                if (nB < NN) {
                    out[(size_t)nB * HH + col] = v10;
                    out[(size_t)nB * HH + col + 1] = v11;
                }
            }
        }
        if (tid < 64) {
            int n = n0 + tid;
            bat[tid] = (n < NN) ? batch[n] : -1;
        }
        __syncthreads();

        // pool reduce: batch is sorted, block spans [b0, blast]
        int col = tid & 127, half = tid >> 7;
        int b0 = bat[0];
        int lastRow = (n0 + 63 < NN) ? 63 : (NN - 1 - n0);
        int blast = bat[lastRow];
        for (int b = b0; b <= blast; b++) {
            float s = 0.f;
            int rbase = half * 32;
#pragma unroll
            for (int r = 0; r < 32; r++) {
                if (bat[rbase + r] == b) s += fbuf[(rbase + r) * 128 + col];
            }
            atomicAdd(&g_pool[b * HH + col], s);
        }
    }
}

// ---------------------------------------------------------------- pool divide
__global__ __launch_bounds__(256) void pooldiv_k(float* __restrict__ out) {
    int i = blockIdx.x * 256 + threadIdx.x;
    if (i < BB * HH) {
        int b = i >> 7;
        float c = (float)g_cnt[b];
        out[(size_t)NN * HH + i] = g_pool[i] / fmaxf(c, 1.f);
    }
}

// ---------------------------------------------------------------- launch
extern "C" void kernel_launch(void* const* d_in, const int* in_sizes, int n_in,
                              void* d_out, int out_size) {
    const float* x      = (const float*)d_in[0];
    const int*   ei     = (const int*)d_in[1];
    const float* ea     = (const float*)d_in[2];
    const int*   batch  = (const int*)d_in[3];
    const float* in_W   = (const float*)d_in[4];
    const float* in_b   = (const float*)d_in[5];
    const float* edge_W = (const float*)d_in[6];
    const float* edge_b = (const float*)d_in[7];
    const float* mlp_W1 = (const float*)d_in[8];
    const float* mlp_b1 = (const float*)d_in[9];
    const float* bn1_g  = (const float*)d_in[10];
    const float* bn1_b  = (const float*)d_in[11];
    const float* bn1_rm = (const float*)d_in[12];
    const float* bn1_rv = (const float*)d_in[13];
    const float* mlp_W2 = (const float*)d_in[14];
    const float* mlp_b2 = (const float*)d_in[15];
    const float* bn2_g  = (const float*)d_in[16];
    const float* bn2_b  = (const float*)d_in[17];
    const float* bn2_rm = (const float*)d_in[18];
    const float* bn2_rv = (const float*)d_in[19];
    const float* epsp   = (const float*)d_in[20];
    const float* ln_g   = (const float*)d_in[21];
    const float* ln_b   = (const float*)d_in[22];
    const float* out_W1 = (const float*)d_in[23];
    const float* out_b1 = (const float*)d_in[24];
    const float* out_W2 = (const float*)d_in[25];
    const float* out_b2 = (const float*)d_in[26];
    float* out = (float*)d_out;

    cudaFuncSetAttribute(mlp_k, cudaFuncAttributeMaxDynamicSharedMemorySize, 100352);
    cudaFuncSetAttribute(out_k, cudaFuncAttributeMaxDynamicSharedMemorySize, 165888);

    // preprocessing (5 launches before first mlp_k)
    zero_misc_k<<<(NN + NPAD + 255) / 256, 256>>>();
    deg_eagg_k<<<(EE + 255) / 256, 256>>>(ei, ea);
    scan_k<<<1, 1024>>>();
    reorder_k<<<(EE + 255) / 256, 256>>>(ei);
    mega_prep_k<<<MP_TOTAL, 256>>>(x, in_W, in_b, mlp_W1, mlp_W2, out_W1, out_W2, batch,
                                   mlp_b1, bn1_g, bn1_b, bn1_rm, bn1_rv,
                                   mlp_b2, bn2_g, bn2_b, bn2_rm, bn2_rv);

    const int NB = (NN + 63) / 64;   // 1563
    for (int l = 0; l < LL; l++) {
        mlp_k<<<NB, 256, 100352>>>(edge_W + l * 3 * HH, edge_b + l * HH,
                                   epsp, ln_g + l * HH, ln_b + l * HH, l);
    }

    out_k<<<NB, 256, 165888>>>(out_b1, out_b2, batch, out);
    pooldiv_k<<<8, 256>>>(out);
}

// round 15
// speedup vs baseline: 2.5241x; 1.1457x over previous
#include <cuda_runtime.h>
#include <cuda_bf16.h>

#define NN 100000
#define EE 600000
#define HH 128
#define LL 3
#define BB 16
#define CATW 512   // (LL+1)*HH
#define NPAD 64    // tail padding rows
#define SB 391     // scan blocks (391*256 >= NN)

// ---- scratch (device globals: no allocation allowed) ----
__device__ float g_cat[(size_t)(NN + NPAD) * CATW];
__device__ int   g_deg[NN];
__device__ int   g_start[NN + 1];
__device__ int   g_cursor[NN];
__device__ int2  g_src2[EE];              // (src, edge_idx) sorted by dst
__device__ int   g_bsum[SB];
__device__ int   g_boff[SB];
__device__ float g_pool[BB * HH];
__device__ int   g_cnt[BB];
// split-bf16 packed weights: uint2 {hi_pair(k,k+1), lo_pair}
__device__ uint2 g_W1p[LL * 64 * 256];
__device__ uint2 g_W2p[LL * 128 * 128];
__device__ uint2 g_oW1p[256 * 128];
__device__ uint2 g_oW2p[64 * 128];
// folded BN: v = acc*a + b
__device__ float g_c1a[LL * 256], g_c1b[LL * 256];
__device__ float g_c2a[LL * 128], g_c2b[LL * 128];

// ---------------------------------------------------------------- helpers
__device__ __forceinline__ uint2 splitpack2(float x0, float x1) {
    __nv_bfloat16 h0 = __float2bfloat16(x0);
    __nv_bfloat16 h1 = __float2bfloat16(x1);
    float r0 = x0 - __bfloat162float(h0);
    float r1 = x1 - __bfloat162float(h1);
    __nv_bfloat16 l0 = __float2bfloat16(r0);
    __nv_bfloat16 l1 = __float2bfloat16(r1);
    unsigned hu = (unsigned)__bfloat16_as_ushort(h0) | ((unsigned)__bfloat16_as_ushort(h1) << 16);
    unsigned lu = (unsigned)__bfloat16_as_ushort(l0) | ((unsigned)__bfloat16_as_ushort(l1) << 16);
    return make_uint2(hu, lu);
}

__device__ __forceinline__ void mma_bf16(float& c0, float& c1, float& c2, float& c3,
                                         unsigned a0, unsigned a1, unsigned a2, unsigned a3,
                                         unsigned b0, unsigned b1) {
    asm volatile("mma.sync.aligned.m16n8k16.row.col.f32.bf16.bf16.f32 "
                 "{%0,%1,%2,%3},{%4,%5,%6,%7},{%8,%9},{%0,%1,%2,%3};\n"
                 : "+f"(c0), "+f"(c1), "+f"(c2), "+f"(c3)
                 : "r"(a0), "r"(a1), "r"(a2), "r"(a3), "r"(b0), "r"(b1));
}

// ---------------------------------------------------------------- misc zero
__global__ __launch_bounds__(256) void zero_misc_k() {
    int i = blockIdx.x * 256 + threadIdx.x;
    if (i < NN) g_deg[i] = 0;
    if (i < BB * HH) g_pool[i] = 0.f;
    if (i < BB) g_cnt[i] = 0;
}

// ---------------------------------------------------------------- degree
__global__ __launch_bounds__(256) void deg_k(const int* __restrict__ ei) {
    int e = blockIdx.x * 256 + threadIdx.x;
    if (e < EE) atomicAdd(&g_deg[ei[EE + e]], 1);
}

// ---------------------------------------------------------------- multi-block scan
__global__ __launch_bounds__(256) void scan1_k() {
    __shared__ int ws[8];
    int tid = threadIdx.x;
    int n = blockIdx.x * 256 + tid;
    int d = (n < NN) ? g_deg[n] : 0;
    int s = d;
#pragma unroll
    for (int o = 16; o; o >>= 1) s += __shfl_xor_sync(0xffffffffu, s, o);
    if ((tid & 31) == 0) ws[tid >> 5] = s;
    __syncthreads();
    if (tid < 8) {
        int v = ws[tid];
#pragma unroll
        for (int o = 4; o; o >>= 1) v += __shfl_xor_sync(0xffu, v, o);
        if (tid == 0) g_bsum[blockIdx.x] = v;
    }
}

__global__ __launch_bounds__(512) void scan2_k() {
    __shared__ int s[512];
    int tid = threadIdx.x;
    int v = (tid < SB) ? g_bsum[tid] : 0;
    s[tid] = v;
    __syncthreads();
    for (int off = 1; off < 512; off <<= 1) {
        int x = s[tid];
        int add = (tid >= off) ? s[tid - off] : 0;
        __syncthreads();
        s[tid] = x + add;
        __syncthreads();
    }
    if (tid < SB) g_boff[tid] = s[tid] - v;   // exclusive
    if (tid == 0) g_start[NN] = EE;
}

__global__ __launch_bounds__(256) void scan3_k() {
    __shared__ int s[256];
    int tid = threadIdx.x;
    int n = blockIdx.x * 256 + tid;
    int d = (n < NN) ? g_deg[n] : 0;
    s[tid] = d;
    __syncthreads();
    for (int off = 1; off < 256; off <<= 1) {
        int x = s[tid];
        int add = (tid >= off) ? s[tid - off] : 0;
        __syncthreads();
        s[tid] = x + add;
        __syncthreads();
    }
    if (n < NN) {
        int st = g_boff[blockIdx.x] + s[tid] - d;   // exclusive
        g_start[n] = st;
        g_cursor[n] = st;
    }
}

// ---------------------------------------------------------------- edge reorder (CSR by dst)
__global__ __launch_bounds__(256) void reorder_k(const int* __restrict__ ei) {
    int e = blockIdx.x * 256 + threadIdx.x;
    if (e >= EE) return;
    int dst = ei[EE + e];
    int pos = atomicAdd(&g_cursor[dst], 1);
    g_src2[pos] = make_int2(ei[e], e);
}

// ---------------------------------------------------------------- fused preprocessing
#define MP_INPROJ 50000
#define MP_PACK   (MP_INPROJ + 544)
#define MP_COUNT  (MP_PACK + 391)
#define MP_TOTAL  (MP_COUNT + 3)

__global__ __launch_bounds__(256) void mega_prep_k(
    const float* __restrict__ x, const float* __restrict__ in_W, const float* __restrict__ in_b,
    const float* __restrict__ mW1, const float* __restrict__ mW2,
    const float* __restrict__ oW1, const float* __restrict__ oW2,
    const int* __restrict__ batch,
    const float* __restrict__ b1, const float* __restrict__ g1, const float* __restrict__ bb1,
    const float* __restrict__ rm1, const float* __restrict__ rv1,
    const float* __restrict__ b2, const float* __restrict__ g2, const float* __restrict__ bb2,
    const float* __restrict__ rm2, const float* __restrict__ rv2) {
    int blk = blockIdx.x;
    int tid = threadIdx.x;

    if (blk < MP_INPROJ) {
        int idx = blk * 256 + tid;
        int n = idx >> 7, c = idx & 127;
        const float* xr = x + n * 12;
        float acc = in_b[c];
#pragma unroll
        for (int k = 0; k < 12; k++) acc += xr[k] * in_W[k * HH + c];
        g_cat[(size_t)n * CATW + c] = acc;
        return;
    }
    if (blk < MP_PACK) {
        int idx = (blk - MP_INPROJ) * 256 + tid;
        if (idx < 49152) {
            int l = idx / 16384, r = idx % 16384;
            int k2 = r / 256, n = r % 256;
            const float* src = mW1 + l * (128 * 256);
            g_W1p[idx] = splitpack2(src[(2 * k2) * 256 + n], src[(2 * k2 + 1) * 256 + n]);
            return;
        }
        int j = idx - 49152;
        if (j < 49152) {
            int l = j / 16384, r = j % 16384;
            int k2 = r / 128, n = r % 128;
            const float* src = mW2 + l * (256 * 128);
            g_W2p[j] = splitpack2(src[(2 * k2) * 128 + n], src[(2 * k2 + 1) * 128 + n]);
            return;
        }
        j -= 49152;
        if (j < 32768) {
            int k2 = j / 128, n = j % 128;
            g_oW1p[j] = splitpack2(oW1[(2 * k2) * 128 + n], oW1[(2 * k2 + 1) * 128 + n]);
            return;
        }
        j -= 32768;
        if (j < 8192) {
            int k2 = j / 128, n = j % 128;
            g_oW2p[j] = splitpack2(oW2[(2 * k2) * 128 + n], oW2[(2 * k2 + 1) * 128 + n]);
        }
        return;
    }
    if (blk < MP_COUNT) {
        __shared__ int sc[BB];
        if (tid < BB) sc[tid] = 0;
        __syncthreads();
        int n = (blk - MP_PACK) * 256 + tid;
        if (n < NN) atomicAdd(&sc[batch[n]], 1);
        __syncthreads();
        if (tid < BB) atomicAdd(&g_cnt[tid], sc[tid]);
        return;
    }
    {
        int i = (blk - MP_COUNT) * 256 + tid;
        if (i < LL * 256) {
            float s = g1[i] * rsqrtf(rv1[i] + 1e-5f);
            g_c1a[i] = s;
            g_c1b[i] = (b1[i] - rm1[i]) * s + bb1[i];
        }
        if (i < LL * 128) {
            float s = g2[i] * rsqrtf(rv2[i] + 1e-5f);
            g_c2a[i] = s;
            g_c2b[i] = (b2[i] - rm2[i]) * s + bb2[i];
        }
    }
}

// ---------------------------------------------------------------- fused GIN layer
// block = 64 nodes, 256 threads (8 warps)
// smem: zsp uint2[64][66] (33792B) | t1p uint2[64][130] (66560B) = 100352B
__global__ __launch_bounds__(256) void mlp_k(const float* __restrict__ ea,
                                             const float* __restrict__ eW,
                                             const float* __restrict__ ebias,
                                             const float* __restrict__ epsp,
                                             const float* __restrict__ lng,
                                             const float* __restrict__ lnb,
                                             int layer) {
    extern __shared__ unsigned char sm_raw[];
    uint2* zsp = (uint2*)sm_raw;                       // [64][66]
    uint2* t1p = (uint2*)(sm_raw + 33792);             // [64][130]
    float* zsf = (float*)sm_raw;                       // alias: [64][132]

    int tid = threadIdx.x;
    int w = tid >> 5, lane = tid & 31;
    int g = lane >> 2, tig = lane & 3;
    int n0 = blockIdx.x * 64;
    float eps1 = 1.f + epsp[layer];

    // ---- stage A: z = (1+eps)h + sum_src (h[src] + ea_e@W_e) + deg*b_e -> zsp
    {
        int c0 = lane * 4;
        float4 ew0 = *(const float4*)&eW[0 * HH + c0];
        float4 ew1 = *(const float4*)&eW[1 * HH + c0];
        float4 ew2 = *(const float4*)&eW[2 * HH + c0];
        float4 eb4 = *(const float4*)&ebias[c0];
        const float* hb = g_cat + layer * HH + c0;
#pragma unroll
        for (int rr = 0; rr < 8; rr++) {
            int rl = w * 8 + rr;
            int n = n0 + rl;
            if (n < NN) {
                float4 h4 = *(const float4*)(hb + (size_t)n * CATW);
                int s0 = g_start[n], s1 = g_start[n + 1];
                float dg = (float)(s1 - s0);
                float ax = eps1 * h4.x + dg * eb4.x;
                float ay = eps1 * h4.y + dg * eb4.y;
                float az = eps1 * h4.z + dg * eb4.z;
                float aw = eps1 * h4.w + dg * eb4.w;
                float e0 = 0.f, e1 = 0.f, e2 = 0.f;   // accumulated edge attrs
                int e = s0;
                for (; e + 2 <= s1; e += 2) {
                    int2 sa = g_src2[e], sb = g_src2[e + 1];
                    float4 va = *(const float4*)(hb + (size_t)sa.x * CATW);
                    float4 vb = *(const float4*)(hb + (size_t)sb.x * CATW);
                    const float* pa = ea + (size_t)sa.y * 3;
                    const float* pb = ea + (size_t)sb.y * 3;
                    e0 += pa[0] + pb[0];
                    e1 += pa[1] + pb[1];
                    e2 += pa[2] + pb[2];
                    ax += va.x + vb.x;
                    ay += va.y + vb.y;
                    az += va.z + vb.z;
                    aw += va.w + vb.w;
                }
                for (; e < s1; e++) {
                    int2 sa = g_src2[e];
                    float4 v = *(const float4*)(hb + (size_t)sa.x * CATW);
                    const float* pa = ea + (size_t)sa.y * 3;
                    e0 += pa[0]; e1 += pa[1]; e2 += pa[2];
                    ax += v.x; ay += v.y; az += v.z; aw += v.w;
                }
                // edge-attr projection once per node (sum of attrs @ W_e)
                ax += e0 * ew0.x + e1 * ew1.x + e2 * ew2.x;
                ay += e0 * ew0.y + e1 * ew1.y + e2 * ew2.y;
                az += e0 * ew0.z + e1 * ew1.z + e2 * ew2.z;
                aw += e0 * ew0.w + e1 * ew1.w + e2 * ew2.w;
                uint2 p0 = splitpack2(ax, ay);
                uint2 p1 = splitpack2(az, aw);
                ((uint4*)zsp)[rl * 33 + lane] = make_uint4(p0.x, p0.y, p1.x, p1.y);
            } else {
                ((uint4*)zsp)[rl * 33 + lane] = make_uint4(0u, 0u, 0u, 0u);
            }
        }
    }
    __syncthreads();

    // ---- GEMM1: [64x128] @ [128x256] -> bn1 relu -> t1p
    {
        const uint2* Wp = g_W1p + layer * (64 * 256);
        int nb = w * 32;
        float c[4][4][4];
#pragma unroll
        for (int rt = 0; rt < 4; rt++)
#pragma unroll
            for (int t = 0; t < 4; t++) { c[rt][t][0] = c[rt][t][1] = c[rt][t][2] = c[rt][t][3] = 0.f; }

        for (int kb2 = 0; kb2 < 64; kb2 += 8) {
            uint2 q0[4], q1[4];
#pragma unroll
            for (int t = 0; t < 4; t++) {
                int n = nb + t * 8 + g;
                q0[t] = Wp[(kb2 + tig) * 256 + n];
                q1[t] = Wp[(kb2 + 4 + tig) * 256 + n];
            }
#pragma unroll
            for (int rt = 0; rt < 4; rt++) {
                int r = rt * 16;
                uint2 r0 = zsp[(r + g) * 66 + kb2 + tig];
                uint2 r1 = zsp[(r + g + 8) * 66 + kb2 + tig];
                uint2 r2 = zsp[(r + g) * 66 + kb2 + 4 + tig];
                uint2 r3 = zsp[(r + g + 8) * 66 + kb2 + 4 + tig];
#pragma unroll
                for (int t = 0; t < 4; t++) {
                    mma_bf16(c[rt][t][0], c[rt][t][1], c[rt][t][2], c[rt][t][3],
                             r0.x, r1.x, r2.x, r3.x, q0[t].x, q1[t].x);
                    mma_bf16(c[rt][t][0], c[rt][t][1], c[rt][t][2], c[rt][t][3],
                             r0.x, r1.x, r2.x, r3.x, q0[t].y, q1[t].y);
                    mma_bf16(c[rt][t][0], c[rt][t][1], c[rt][t][2], c[rt][t][3],
                             r0.y, r1.y, r2.y, r3.y, q0[t].x, q1[t].x);
                }
            }
        }
        const float* A1 = g_c1a + layer * 256;
        const float* B1 = g_c1b + layer * 256;
#pragma unroll
        for (int rt = 0; rt < 4; rt++) {
#pragma unroll
            for (int t = 0; t < 4; t++) {
                int col = nb + t * 8 + tig * 2;
                float a0 = A1[col], b0 = B1[col], a1 = A1[col + 1], b1 = B1[col + 1];
                float v00 = fmaxf(c[rt][t][0] * a0 + b0, 0.f);
                float v01 = fmaxf(c[rt][t][1] * a1 + b1, 0.f);
                float v10 = fmaxf(c[rt][t][2] * a0 + b0, 0.f);
                float v11 = fmaxf(c[rt][t][3] * a1 + b1, 0.f);
                int c2 = col >> 1;
                t1p[(rt * 16 + g) * 130 + c2] = splitpack2(v00, v01);
                t1p[(rt * 16 + g + 8) * 130 + c2] = splitpack2(v10, v11);
            }
        }
    }
    __syncthreads();

    // ---- GEMM2: [64x256] @ [256x128] -> bn2 relu + residual -> zsf
    {
        const uint2* Wp = g_W2p + layer * (128 * 128);
        int nb = w * 16;
        float c[4][2][4];
#pragma unroll
        for (int rt = 0; rt < 4; rt++)
#pragma unroll
            for (int t = 0; t < 2; t++) { c[rt][t][0] = c[rt][t][1] = c[rt][t][2] = c[rt][t][3] = 0.f; }

        for (int kb2 = 0; kb2 < 128; kb2 += 8) {
            uint2 q0[2], q1[2];
#pragma unroll
            for (int t = 0; t < 2; t++) {
                int n = nb + t * 8 + g;
                q0[t] = Wp[(kb2 + tig) * 128 + n];
                q1[t] = Wp[(kb2 + 4 + tig) * 128 + n];
            }
#pragma unroll
            for (int rt = 0; rt < 4; rt++) {
                int r = rt * 16;
                uint2 r0 = t1p[(r + g) * 130 + kb2 + tig];
                uint2 r1 = t1p[(r + g + 8) * 130 + kb2 + tig];
                uint2 r2 = t1p[(r + g) * 130 + kb2 + 4 + tig];
                uint2 r3 = t1p[(r + g + 8) * 130 + kb2 + 4 + tig];
#pragma unroll
                for (int t = 0; t < 2; t++) {
                    mma_bf16(c[rt][t][0], c[rt][t][1], c[rt][t][2], c[rt][t][3],
                             r0.x, r1.x, r2.x, r3.x, q0[t].x, q1[t].x);
                    mma_bf16(c[rt][t][0], c[rt][t][1], c[rt][t][2], c[rt][t][3],
                             r0.x, r1.x, r2.x, r3.x, q0[t].y, q1[t].y);
                    mma_bf16(c[rt][t][0], c[rt][t][1], c[rt][t][2], c[rt][t][3],
                             r0.y, r1.y, r2.y, r3.y, q0[t].x, q1[t].x);
                }
            }
        }
        const float* A2 = g_c2a + layer * 128;
        const float* B2 = g_c2b + layer * 128;
#pragma unroll
        for (int rt = 0; rt < 4; rt++) {
#pragma unroll
            for (int t = 0; t < 2; t++) {
                int col = nb + t * 8 + tig * 2;
                float a0 = A2[col], b0 = B2[col], a1 = A2[col + 1], b1 = B2[col + 1];
                int r0w = rt * 16 + g, r1w = rt * 16 + g + 8;
                const float* h0 = g_cat + (size_t)(n0 + r0w) * CATW + layer * HH + col;
                const float* h1 = g_cat + (size_t)(n0 + r1w) * CATW + layer * HH + col;
                zsf[r0w * 132 + col]     = fmaxf(c[rt][t][0] * a0 + b0, 0.f) + h0[0];
                zsf[r0w * 132 + col + 1] = fmaxf(c[rt][t][1] * a1 + b1, 0.f) + h0[1];
                zsf[r1w * 132 + col]     = fmaxf(c[rt][t][2] * a0 + b0, 0.f) + h1[0];
                zsf[r1w * 132 + col + 1] = fmaxf(c[rt][t][3] * a1 + b1, 0.f) + h1[1];
            }
        }
    }
    __syncthreads();

    // ---- LayerNorm rows -> g_cat layer+1
    {
#pragma unroll
        for (int rr = 0; rr < 8; rr++) {
            int m = w * 8 + rr;
            float4 v = *(const float4*)&zsf[m * 132 + lane * 4];
            float sum = v.x + v.y + v.z + v.w;
            float sq = v.x * v.x + v.y * v.y + v.z * v.z + v.w * v.w;
#pragma unroll
            for (int o = 16; o; o >>= 1) {
                sum += __shfl_xor_sync(0xffffffffu, sum, o);
                sq += __shfl_xor_sync(0xffffffffu, sq, o);
            }
            float mu = sum * (1.f / 128.f);
            float var = sq * (1.f / 128.f) - mu * mu;
            float inv = rsqrtf(var + 1e-5f);
            int n = n0 + m;
            if (n < NN) {
                int c0 = lane * 4;
                float4 o;
                o.x = (v.x - mu) * inv * lng[c0 + 0] + lnb[c0 + 0];
                o.y = (v.y - mu) * inv * lng[c0 + 1] + lnb[c0 + 1];
                o.z = (v.z - mu) * inv * lng[c0 + 2] + lnb[c0 + 2];
                o.w = (v.w - mu) * inv * lng[c0 + 3] + lnb[c0 + 3];
                *(float4*)&g_cat[(size_t)n * CATW + (layer + 1) * HH + c0] = o;
            }
        }
    }
}

// ---------------------------------------------------------------- output head
// block = 64 nodes; split-K staging: catp uint2[64][130] (66560B) | t1p uint2[64][66] (33792B)
// = 100352B -> 2 CTAs/SM.  After GEMM2: region 0 reused as fbuf float[64][128] + bat int[64].
__global__ __launch_bounds__(256) void out_k(const float* __restrict__ ob1,
                                             const float* __restrict__ ob2,
                                             const int* __restrict__ batch,
                                             float* __restrict__ out) {
    extern __shared__ unsigned char sm_raw[];
    uint2* catp = (uint2*)sm_raw;                   // [64][130]
    uint2* t1p = (uint2*)(sm_raw + 66560);          // [64][66]

    int tid = threadIdx.x;
    int w = tid >> 5, lane = tid & 31;
    int g = lane >> 2, tig = lane & 3;
    int n0 = blockIdx.x * 64;
    int nb = w * 16;

    // GEMM1: [64x512] @ [512x128] in two K-halves -> relu -> t1p
    float c1[4][2][4];
#pragma unroll
    for (int rt = 0; rt < 4; rt++)
#pragma unroll
        for (int t = 0; t < 2; t++) { c1[rt][t][0] = c1[rt][t][1] = c1[rt][t][2] = c1[rt][t][3] = 0.f; }

    for (int half = 0; half < 2; half++) {
        if (half) __syncthreads();   // prev GEMM reads of catp complete
        // stage 64x256 slice (padded g_cat: unguarded reads OK)
#pragma unroll
        for (int i = 0; i < 16; i++) {
            int idx = tid + i * 256;          // 0..4095 (64 rows x 64 float4)
            int n = idx >> 6, c4 = idx & 63;
            float4 v = *(const float4*)(g_cat + (size_t)(n0 + n) * CATW + half * 256 + c4 * 4);
            uint2 p0 = splitpack2(v.x, v.y);
            uint2 p1 = splitpack2(v.z, v.w);
            ((uint4*)catp)[n * 65 + c4] = make_uint4(p0.x, p0.y, p1.x, p1.y);
        }
        __syncthreads();

        for (int kb2 = 0; kb2 < 128; kb2 += 8) {
            int kg = half * 128 + kb2;
            uint2 q0[2], q1[2];
#pragma unroll
            for (int t = 0; t < 2; t++) {
                int n = nb + t * 8 + g;
                q0[t] = g_oW1p[(kg + tig) * 128 + n];
                q1[t] = g_oW1p[(kg + 4 + tig) * 128 + n];
            }
#pragma unroll
            for (int rt = 0; rt < 4; rt++) {
                int r = rt * 16;
                uint2 r0 = catp[(r + g) * 130 + kb2 + tig];
                uint2 r1 = catp[(r + g + 8) * 130 + kb2 + tig];
                uint2 r2 = catp[(r + g) * 130 + kb2 + 4 + tig];
                uint2 r3 = catp[(r + g + 8) * 130 + kb2 + 4 + tig];
#pragma unroll
                for (int t = 0; t < 2; t++) {
                    mma_bf16(c1[rt][t][0], c1[rt][t][1], c1[rt][t][2], c1[rt][t][3],
                             r0.x, r1.x, r2.x, r3.x, q0[t].x, q1[t].x);
                    mma_bf16(c1[rt][t][0], c1[rt][t][1], c1[rt][t][2], c1[rt][t][3],
                             r0.x, r1.x, r2.x, r3.x, q0[t].y, q1[t].y);
                    mma_bf16(c1[rt][t][0], c1[rt][t][1], c1[rt][t][2], c1[rt][t][3],
                             r0.y, r1.y, r2.y, r3.y, q0[t].x, q1[t].x);
                }
            }
        }
    }
    // epilogue1 -> t1p (t1p region untouched by GEMM1)
#pragma unroll
    for (int rt = 0; rt < 4; rt++) {
#pragma unroll
        for (int t = 0; t < 2; t++) {
            int col = nb + t * 8 + tig * 2;
            float b0 = ob1[col], b1 = ob1[col + 1];
            float v00 = fmaxf(c1[rt][t][0] + b0, 0.f);
            float v01 = fmaxf(c1[rt][t][1] + b1, 0.f);
            float v10 = fmaxf(c1[rt][t][2] + b0, 0.f);
            float v11 = fmaxf(c1[rt][t][3] + b1, 0.f);
            int c2 = col >> 1;
            t1p[(rt * 16 + g) * 66 + c2] = splitpack2(v00, v01);
            t1p[(rt * 16 + g + 8) * 66 + c2] = splitpack2(v10, v11);
        }
    }
    __syncthreads();

    // GEMM2: [64x128] @ [128x128]
    float c[4][2][4];
    {
#pragma unroll
        for (int rt = 0; rt < 4; rt++)
#pragma unroll
            for (int t = 0; t < 2; t++) { c[rt][t][0] = c[rt][t][1] = c[rt][t][2] = c[rt][t][3] = 0.f; }

        for (int kb2 = 0; kb2 < 64; kb2 += 8) {
            uint2 q0[2], q1[2];
#pragma unroll
            for (int t = 0; t < 2; t++) {
                int n = nb + t * 8 + g;
                q0[t] = g_oW2p[(kb2 + tig) * 128 + n];
                q1[t] = g_oW2p[(kb2 + 4 + tig) * 128 + n];
            }
#pragma unroll
            for (int rt = 0; rt < 4; rt++) {
                int r = rt * 16;
                uint2 r0 = t1p[(r + g) * 66 + kb2 + tig];
                uint2 r1 = t1p[(r + g + 8) * 66 + kb2 + tig];
                uint2 r2 = t1p[(r + g) * 66 + kb2 + 4 + tig];
                uint2 r3 = t1p[(r + g + 8) * 66 + kb2 + 4 + tig];
#pragma unroll
                for (int t = 0; t < 2; t++) {
                    mma_bf16(c[rt][t][0], c[rt][t][1], c[rt][t][2], c[rt][t][3],
                             r0.x, r1.x, r2.x, r3.x, q0[t].x, q1[t].x);
                    mma_bf16(c[rt][t][0], c[rt][t][1], c[rt][t][2], c[rt][t][3],
                             r0.x, r1.x, r2.x, r3.x, q0[t].y, q1[t].y);
                    mma_bf16(c[rt][t][0], c[rt][t][1], c[rt][t][2], c[rt][t][3],
                             r0.y, r1.y, r2.y, r3.y, q0[t].x, q1[t].x);
                }
            }
        }
    }
    __syncthreads();   // all GEMM reads done -> safe to reuse region 0

    // epilogue: write out + stage node_emb into smem fbuf, then batched pool reduce
    {
        float* fbuf = (float*)sm_raw;             // [64][128]
        int* bat = (int*)(sm_raw + 32768);        // [64]
#pragma unroll
        for (int rt = 0; rt < 4; rt++) {
            int rA = rt * 16 + g, rB = rA + 8;
            int nA = n0 + rA, nB = n0 + rB;
#pragma unroll
            for (int t = 0; t < 2; t++) {
                int col = nb + t * 8 + tig * 2;
                float b0 = ob2[col], b1 = ob2[col + 1];
                float v00 = c[rt][t][0] + b0, v01 = c[rt][t][1] + b1;
                float v10 = c[rt][t][2] + b0, v11 = c[rt][t][3] + b1;
                fbuf[rA * 128 + col] = v00;
                fbuf[rA * 128 + col + 1] = v01;
                fbuf[rB * 128 + col] = v10;
                fbuf[rB * 128 + col + 1] = v11;
                if (nA < NN) {
                    out[(size_t)nA * HH + col] = v00;
                    out[(size_t)nA * HH + col + 1] = v01;
                }
                if (nB < NN) {
                    out[(size_t)nB * HH + col] = v10;
                    out[(size_t)nB * HH + col + 1] = v11;
                }
            }
        }
        if (tid < 64) {
            int n = n0 + tid;
            bat[tid] = (n < NN) ? batch[n] : -1;
        }
        __syncthreads();

        // pool reduce: batch is sorted, block spans [b0, blast]
        int col = tid & 127, half = tid >> 7;
        int b0 = bat[0];
        int lastRow = (n0 + 63 < NN) ? 63 : (NN - 1 - n0);
        int blast = bat[lastRow];
        for (int b = b0; b <= blast; b++) {
            float s = 0.f;
            int rbase = half * 32;
#pragma unroll
            for (int r = 0; r < 32; r++) {
                if (bat[rbase + r] == b) s += fbuf[(rbase + r) * 128 + col];
            }
            atomicAdd(&g_pool[b * HH + col], s);
        }
    }
}

// ---------------------------------------------------------------- pool divide
__global__ __launch_bounds__(256) void pooldiv_k(float* __restrict__ out) {
    int i = blockIdx.x * 256 + threadIdx.x;
    if (i < BB * HH) {
        int b = i >> 7;
        float c = (float)g_cnt[b];
        out[(size_t)NN * HH + i] = g_pool[i] / fmaxf(c, 1.f);
    }
}

// ---------------------------------------------------------------- launch
extern "C" void kernel_launch(void* const* d_in, const int* in_sizes, int n_in,
                              void* d_out, int out_size) {
    const float* x      = (const float*)d_in[0];
    const int*   ei     = (const int*)d_in[1];
    const float* ea     = (const float*)d_in[2];
    const int*   batch  = (const int*)d_in[3];
    const float* in_W   = (const float*)d_in[4];
    const float* in_b   = (const float*)d_in[5];
    const float* edge_W = (const float*)d_in[6];
    const float* edge_b = (const float*)d_in[7];
    const float* mlp_W1 = (const float*)d_in[8];
    const float* mlp_b1 = (const float*)d_in[9];
    const float* bn1_g  = (const float*)d_in[10];
    const float* bn1_b  = (const float*)d_in[11];
    const float* bn1_rm = (const float*)d_in[12];
    const float* bn1_rv = (const float*)d_in[13];
    const float* mlp_W2 = (const float*)d_in[14];
    const float* mlp_b2 = (const float*)d_in[15];
    const float* bn2_g  = (const float*)d_in[16];
    const float* bn2_b  = (const float*)d_in[17];
    const float* bn2_rm = (const float*)d_in[18];
    const float* bn2_rv = (const float*)d_in[19];
    const float* epsp   = (const float*)d_in[20];
    const float* ln_g   = (const float*)d_in[21];
    const float* ln_b   = (const float*)d_in[22];
    const float* out_W1 = (const float*)d_in[23];
    const float* out_b1 = (const float*)d_in[24];
    const float* out_W2 = (const float*)d_in[25];
    const float* out_b2 = (const float*)d_in[26];
    float* out = (float*)d_out;

    cudaFuncSetAttribute(mlp_k, cudaFuncAttributeMaxDynamicSharedMemorySize, 100352);
    cudaFuncSetAttribute(out_k, cudaFuncAttributeMaxDynamicSharedMemorySize, 100352);

    // preprocessing
    zero_misc_k<<<(NN + 255) / 256, 256>>>();
    deg_k<<<(EE + 255) / 256, 256>>>(ei);
    scan1_k<<<SB, 256>>>();
    scan2_k<<<1, 512>>>();
    scan3_k<<<SB, 256>>>();
    reorder_k<<<(EE + 255) / 256, 256>>>(ei);
    mega_prep_k<<<MP_TOTAL, 256>>>(x, in_W, in_b, mlp_W1, mlp_W2, out_W1, out_W2, batch,
                                   mlp_b1, bn1_g, bn1_b, bn1_rm, bn1_rv,
                                   mlp_b2, bn2_g, bn2_b, bn2_rm, bn2_rv);

    const int NB = (NN + 63) / 64;   // 1563
    for (int l = 0; l < LL; l++) {
        mlp_k<<<NB, 256, 100352>>>(ea, edge_W + l * 3 * HH, edge_b + l * HH,
                                   epsp, ln_g + l * HH, ln_b + l * HH, l);
    }

    out_k<<<NB, 256, 100352>>>(out_b1, out_b2, batch, out);
    pooldiv_k<<<8, 256>>>(out);
}